// round 12
// baseline (speedup 1.0000x reference)
#include <cuda_runtime.h>
#include <cuda_fp16.h>
#include <cstdint>

#define NOBJ 20000
#define NTRI 100000
#define DIM  512

// ---------------- static device scratch (allocation-free) ----------------
__device__ __half g_hh[(size_t)NTRI * DIM];
__device__ float  g_pooled[(size_t)NOBJ * DIM];
__device__ __half g_poolh[(size_t)NOBJ * DIM];
__device__ __half g_gh[(size_t)NOBJ * DIM];
__device__ float  g_counts[NOBJ];
__device__ __half g_objh[(size_t)NOBJ * DIM];
__device__ __half g_predh[(size_t)NTRI * DIM];
__device__ __half g_tach[(size_t)NOBJ * 1024];  // [T_a | T_c] merged
__device__ __half g_W1h[512 * 1536];
__device__ __half g_W2h[1536 * 512];
__device__ __half g_V1h[512 * 512];
__device__ __half g_V2h[512 * 512];
__device__ __half g_Poh[512 * 512];
__device__ __half g_Pph[512 * 512];

// ---------------- helpers ----------------
__device__ __forceinline__ uint32_t smem_u32(const void* p) {
    uint32_t a;
    asm("{ .reg .u64 t; cvta.to.shared.u64 t, %1; cvt.u32.u64 %0, t; }" : "=r"(a) : "l"(p));
    return a;
}
__device__ __forceinline__ void cp16(uint32_t sdst, const void* gsrc) {
    asm volatile("cp.async.cg.shared.global [%0], [%1], 16;" :: "r"(sdst), "l"(gsrc) : "memory");
}
__device__ __forceinline__ void cp_commit() {
    asm volatile("cp.async.commit_group;" ::: "memory");
}
__device__ __forceinline__ void ldsm4(uint32_t* r, uint32_t addr) {
    asm volatile("ldmatrix.sync.aligned.m8n8.x4.shared.b16 {%0,%1,%2,%3}, [%4];"
                 : "=r"(r[0]), "=r"(r[1]), "=r"(r[2]), "=r"(r[3]) : "r"(addr));
}
// non-volatile: lets ptxas interleave MMAs with LDSMs
__device__ __forceinline__ void mma16816(float* d, const uint32_t* a, const uint32_t* b) {
    asm("mma.sync.aligned.m16n8k16.row.col.f32.f16.f16.f32 "
        "{%0,%1,%2,%3}, {%4,%5,%6,%7}, {%8,%9}, {%0,%1,%2,%3};"
        : "+f"(d[0]), "+f"(d[1]), "+f"(d[2]), "+f"(d[3])
        : "r"(a[0]), "r"(a[1]), "r"(a[2]), "r"(a[3]), "r"(b[0]), "r"(b[1]));
}
__device__ __forceinline__ void red2(float* p, float x, float y) {
    asm volatile("red.global.add.v2.f32 [%0], {%1,%2};"
                 :: "l"(p), "f"(x), "f"(y) : "memory");
}
__device__ __forceinline__ uint2 cvt4(float4 v) {
    __half2 h0 = __floats2half2_rn(v.x, v.y);
    __half2 h1 = __floats2half2_rn(v.z, v.w);
    uint2 u;
    u.x = *reinterpret_cast<uint32_t*>(&h0);
    u.y = *reinterpret_cast<uint32_t*>(&h1);
    return u;
}

// ---------------- GEMM config ----------------
constexpr int BM = 128, BN = 128, BK = 64;   // BK in halves (64 = 8 stages for K=512)
constexpr int LDA = 72;                      // smem row stride (halves); 144B rows, conflict-free
constexpr int NSTG = 3;
constexpr int A_BYTES = BM * LDA * 2;        // 18432
constexpr int B_BYTES = BN * LDA * 2;        // 18432
constexpr int STG_BYTES = A_BYTES + B_BYTES; // 36864
constexpr int SMEM_BYTES = NSTG * STG_BYTES; // 110592 -> 2 CTAs/SM (221KB of 228KB)
constexpr int NTHR = 256;                    // 8 warps, 2x4, 64x32 warp tile

// ---------------- fp16 MMA GEMM: epi(A[M,K] @ B[N,K_ldb]^T + bias) ----------------
// MODE 0: Ch = relu(v+bias) half
// MODE 2: region = colBlock>>9: 0 -> red2 pooled[s]; 1 -> outp; 2 -> red2 pooled[o]  (relu)
// MODE 3: Cf = relu(v+bias) float
// MODE 4: Ch = relu(v + bias + tah[edges[2r]*1024+c] + tch[edges[2r+1]*1024+c]) half
// MODE 6: Ch = v half (no bias/relu); split-B: col n<512 -> B+n*ldb, n>=512 -> B+(n-512)*ldb+1024
// MODE 7: two residual GEMMs row-partitioned: blockIdx.y < ceil(M/128) -> (A,B,bias,Cf,M)
//         else -> (tah as A2, tch as B2, bias2, Cf2, M2)
template <int MODE>
__global__ void __launch_bounds__(NTHR, 2)
gemm_h(const __half* __restrict__ A, const __half* __restrict__ B, int ldb,
       const float* __restrict__ bias,
       __half* __restrict__ Ch, float* __restrict__ Cf,
       int M, int N, int K,
       const int* __restrict__ edges,
       const __half* __restrict__ tah, const __half* __restrict__ tch,
       float* __restrict__ pooled, float* __restrict__ outp,
       const float* __restrict__ bias2, float* __restrict__ Cf2, int M2)
{
    extern __shared__ __align__(16) char dynsmem[];
    const uint32_t sbase = smem_u32(dynsmem);

    const int tid = threadIdx.x;
    const int wid = tid >> 5, lane = tid & 31;
    const int wm = wid & 1;          // 2 warp rows (64 rows each)
    const int wn = wid >> 1;         // 4 warp cols (32 cols each)

    // ---- MODE 7 dual-GEMM selection ----
    const __half* AP = A;
    const __half* BP = B;
    const float*  biasP = bias;
    float*        CfP = Cf;
    int rowBlockY = blockIdx.y;
    if (MODE == 7) {
        const int blocks0 = (M + BM - 1) >> 7;
        if ((int)blockIdx.y >= blocks0) {
            AP = tah; BP = tch; biasP = bias2; CfP = Cf2;
            M = M2; rowBlockY = blockIdx.y - blocks0;
        }
    }
    const int rowBlock = rowBlockY * BM;
    const int colBlock = blockIdx.x * BN;

    // ---- loader mapping: 2 threads per row, 32 halves (4 cp16) each ----
    const int lrow = tid >> 1;               // 0..127
    const int lhs  = (tid & 1) * 32;         // halves
    const int gr  = rowBlock + lrow;
    const int grc = gr < M ? gr : (M - 1);
    const __half* arowp = AP + (size_t)grc * K;
    const __half* browp;
    if (MODE == 6) {
        const int n = colBlock + lrow;
        browp = BP + (size_t)(n & 511) * ldb + ((n >= 512) ? 1024 : 0);
    } else {
        browp = BP + (size_t)(colBlock + lrow) * ldb;
    }

    const uint32_t aDst = sbase + (uint32_t)(lrow * LDA + lhs) * 2;
    const uint32_t bDst = sbase + (uint32_t)A_BYTES + (uint32_t)(lrow * LDA + lhs) * 2;

    auto load_stage = [&](int i, int buf) {
        const uint32_t so = (uint32_t)(buf * STG_BYTES);
        const int kb = (i << 6) + lhs;
        {
            const __half* src = arowp + kb;
            cp16(aDst + so,      src);
            cp16(aDst + so + 16, src + 8);
            cp16(aDst + so + 32, src + 16);
            cp16(aDst + so + 48, src + 24);
        }
        {
            const __half* src = browp + kb;
            cp16(bDst + so,      src);
            cp16(bDst + so + 16, src + 8);
            cp16(bDst + so + 32, src + 16);
            cp16(bDst + so + 48, src + 24);
        }
        cp_commit();
    };

    // ---- fragment lane addressing (byte offsets within a stage) ----
    const uint32_t aFrag = sbase
        + (uint32_t)(((wm * 64 + (lane & 15)) * LDA + ((lane >> 4) << 3)) * 2);
    const uint32_t bFrag = sbase + (uint32_t)A_BYTES
        + (uint32_t)(((wn * 32 + ((lane & 7) | ((lane >> 4) << 3))) * LDA
                      + (((lane >> 3) & 1) << 3)) * 2);

    float acc[4][4][4];
#pragma unroll
    for (int i = 0; i < 4; i++)
#pragma unroll
        for (int j = 0; j < 4; j++)
#pragma unroll
            for (int q = 0; q < 4; q++) acc[i][j][q] = 0.f;

    const int nst = K >> 6;   // 8 stages for K=512

    load_stage(0, 0);
    load_stage(1, 1);

    int buf = 0;
    for (int i = 0; i < nst; i++) {
        if (i >= nst - 1) asm volatile("cp.async.wait_group 0;" ::: "memory");
        else              asm volatile("cp.async.wait_group 1;" ::: "memory");
        __syncthreads();

        if (i + 2 < nst) {
            int nb = buf + 2; if (nb >= NSTG) nb -= NSTG;
            load_stage(i + 2, nb);
        }

        const uint32_t so = (uint32_t)(buf * STG_BYTES);
        // A-fragment streaming within each kk-quarter (4 kk x [2 LDSM B + 4x(LDSM A + 4 MMA)])
#pragma unroll
        for (int kk = 0; kk < 4; kk++) {
            uint32_t b[2][4];
            ldsm4(b[0], bFrag + so + (uint32_t)((kk * 16) * 2));
            ldsm4(b[1], bFrag + so + (uint32_t)((16 * LDA + kk * 16) * 2));
#pragma unroll
            for (int mt = 0; mt < 4; mt++) {
                uint32_t a[4];
                ldsm4(a, aFrag + so + (uint32_t)((mt * 16 * LDA + kk * 16) * 2));
#pragma unroll
                for (int nt = 0; nt < 4; nt++)
                    mma16816(acc[mt][nt], a, &b[nt >> 1][(nt & 1) * 2]);
            }
        }

        buf++; if (buf >= NSTG) buf -= NSTG;
    }

    // ---- epilogue ----
    const int region = colBlock >> 9;
#pragma unroll
    for (int mt = 0; mt < 4; mt++) {
        const int r0 = rowBlock + wm * 64 + mt * 16 + (lane >> 2);
        const int r1 = r0 + 8;
        const bool ok0 = r0 < M, ok1 = r1 < M;
        int s0 = 0, o0 = 0, s1 = 0, o1 = 0;
        if (MODE == 2) {
            if (region == 0) {
                if (ok0) s0 = edges[2 * r0];
                if (ok1) s1 = edges[2 * r1];
            } else if (region == 2) {
                if (ok0) o0 = edges[2 * r0 + 1];
                if (ok1) o1 = edges[2 * r1 + 1];
            }
        } else if (MODE == 4) {
            if (ok0) { s0 = edges[2 * r0]; o0 = edges[2 * r0 + 1]; }
            if (ok1) { s1 = edges[2 * r1]; o1 = edges[2 * r1 + 1]; }
        }
#pragma unroll
        for (int nt = 0; nt < 4; nt++) {
            const int c = colBlock + wn * 32 + nt * 8 + 2 * (lane & 3);
            float bx = 0.f, by = 0.f;
            if (MODE != 6) { bx = biasP[c]; by = biasP[c + 1]; }
            float v00 = acc[mt][nt][0] + bx, v01 = acc[mt][nt][1] + by;
            float v10 = acc[mt][nt][2] + bx, v11 = acc[mt][nt][3] + by;
            if (MODE == 0 || MODE == 2 || MODE == 3) {
                v00 = fmaxf(v00, 0.f); v01 = fmaxf(v01, 0.f);
                v10 = fmaxf(v10, 0.f); v11 = fmaxf(v11, 0.f);
            }
            if (MODE == 0 || MODE == 6) {
                if (ok0) *reinterpret_cast<__half2*>(Ch + (size_t)r0 * N + c) = __floats2half2_rn(v00, v01);
                if (ok1) *reinterpret_cast<__half2*>(Ch + (size_t)r1 * N + c) = __floats2half2_rn(v10, v11);
            } else if (MODE == 4) {
                if (ok0) {
                    __half2 ta = *reinterpret_cast<const __half2*>(tah + (size_t)s0 * 1024 + c);
                    __half2 tc = *reinterpret_cast<const __half2*>(tch + (size_t)o0 * 1024 + c);
                    float w0 = fmaxf(v00 + __low2float(ta) + __low2float(tc), 0.f);
                    float w1 = fmaxf(v01 + __high2float(ta) + __high2float(tc), 0.f);
                    *reinterpret_cast<__half2*>(Ch + (size_t)r0 * N + c) = __floats2half2_rn(w0, w1);
                }
                if (ok1) {
                    __half2 ta = *reinterpret_cast<const __half2*>(tah + (size_t)s1 * 1024 + c);
                    __half2 tc = *reinterpret_cast<const __half2*>(tch + (size_t)o1 * 1024 + c);
                    float w0 = fmaxf(v10 + __low2float(ta) + __low2float(tc), 0.f);
                    float w1 = fmaxf(v11 + __high2float(ta) + __high2float(tc), 0.f);
                    *reinterpret_cast<__half2*>(Ch + (size_t)r1 * N + c) = __floats2half2_rn(w0, w1);
                }
            } else if (MODE == 3) {
                if (ok0) *reinterpret_cast<float2*>(Cf + (size_t)r0 * N + c) = make_float2(v00, v01);
                if (ok1) *reinterpret_cast<float2*>(Cf + (size_t)r1 * N + c) = make_float2(v10, v11);
            } else if (MODE == 7) {
                if (ok0) {
                    float2 o = *reinterpret_cast<const float2*>(CfP + (size_t)r0 * N + c);
                    *reinterpret_cast<float2*>(CfP + (size_t)r0 * N + c) = make_float2(o.x + v00, o.y + v01);
                }
                if (ok1) {
                    float2 o = *reinterpret_cast<const float2*>(CfP + (size_t)r1 * N + c);
                    *reinterpret_cast<float2*>(CfP + (size_t)r1 * N + c) = make_float2(o.x + v10, o.y + v11);
                }
            } else { // MODE 2
                const int cl = c & 511;
                if (region == 1) {
                    if (ok0) *reinterpret_cast<float2*>(outp + (size_t)r0 * DIM + cl) = make_float2(v00, v01);
                    if (ok1) *reinterpret_cast<float2*>(outp + (size_t)r1 * DIM + cl) = make_float2(v10, v11);
                } else if (region == 0) {
                    if (ok0) red2(&pooled[(size_t)s0 * DIM + cl], v00, v01);
                    if (ok1) red2(&pooled[(size_t)s1 * DIM + cl], v10, v11);
                } else {
                    if (ok0) red2(&pooled[(size_t)o0 * DIM + cl], v00, v01);
                    if (ok1) red2(&pooled[(size_t)o1 * DIM + cl], v10, v11);
                }
            }
        }
    }
}

// ---------------- merged prep kernels ----------------
constexpr size_t PA0 = 2560000;            // obj f4 count
constexpr size_t PA1 = PA0 + 12800000;     // + pred f4
__global__ void prep_a_kernel(const float4* __restrict__ objv, const float4* __restrict__ predv,
                              uint2* __restrict__ objh, uint2* __restrict__ predh)
{
    size_t i = (size_t)blockIdx.x * blockDim.x + threadIdx.x;
    if (i < PA0)      objh[i] = cvt4(objv[i]);
    else if (i < PA1) predh[i - PA0] = cvt4(predv[i - PA0]);
}

constexpr size_t PB0 = 196608;             // W1 f4
constexpr size_t PB1 = PB0 + 196608;       // W2
constexpr size_t PB2 = PB1 + 65536;        // V1
constexpr size_t PB3 = PB2 + 65536;        // V2
constexpr size_t PB4 = PB3 + 65536;        // Po
constexpr size_t PB5 = PB4 + 65536;        // Pp
constexpr size_t PB6 = PB5 + 2560000;      // zero pooled (f4)
constexpr size_t PB7 = PB6 + 5000;         // zero counts (f4)
__global__ void prep_b_kernel(const float4* __restrict__ W1, const float4* __restrict__ W2,
                              const float4* __restrict__ V1, const float4* __restrict__ V2,
                              const float4* __restrict__ Po, const float4* __restrict__ Pp,
                              uint2* __restrict__ w1h, uint2* __restrict__ w2h,
                              uint2* __restrict__ v1h, uint2* __restrict__ v2h,
                              uint2* __restrict__ poh, uint2* __restrict__ pph,
                              float4* __restrict__ pooled, float4* __restrict__ counts)
{
    size_t i = (size_t)blockIdx.x * blockDim.x + threadIdx.x;
    if (i < PB0)      w1h[i] = cvt4(W1[i]);
    else if (i < PB1) w2h[i - PB0] = cvt4(W2[i - PB0]);
    else if (i < PB2) v1h[i - PB1] = cvt4(V1[i - PB1]);
    else if (i < PB3) v2h[i - PB2] = cvt4(V2[i - PB2]);
    else if (i < PB4) poh[i - PB3] = cvt4(Po[i - PB3]);
    else if (i < PB5) pph[i - PB4] = cvt4(Pp[i - PB4]);
    else if (i < PB6) pooled[i - PB5] = make_float4(0.f, 0.f, 0.f, 0.f);
    else if (i < PB7) counts[i - PB6] = make_float4(0.f, 0.f, 0.f, 0.f);
}

__global__ void count_kernel(const int* __restrict__ edges, float* counts) {
    int i = blockIdx.x * blockDim.x + threadIdx.x;
    if (i < NTRI) {
        atomicAdd(&counts[edges[2 * i]], 1.f);
        atomicAdd(&counts[edges[2 * i + 1]], 1.f);
    }
}

__global__ void normalize_kernel(const float* __restrict__ pooled,
                                 const float* __restrict__ counts,
                                 __half* __restrict__ poolh) {
    int i = blockIdx.x * blockDim.x + threadIdx.x;
    if (i < NOBJ * DIM) {
        float c = counts[i >> 9];
        poolh[i] = __float2half_rn(pooled[i] * (1.f / fmaxf(c, 1.f)));
    }
}

// ---------------- launcher ----------------
extern "C" void kernel_launch(void* const* d_in, const int* in_sizes, int n_in,
                              void* d_out, int out_size)
{
    const float* objv    = (const float*)d_in[0];
    const float* predv   = (const float*)d_in[1];
    const int*   edges   = (const int*)  d_in[2];
    const float* W1      = (const float*)d_in[3];
    const float* b1      = (const float*)d_in[4];
    const float* W2      = (const float*)d_in[5];
    const float* b2      = (const float*)d_in[6];
    const float* V1      = (const float*)d_in[7];
    const float* c1      = (const float*)d_in[8];
    const float* V2      = (const float*)d_in[9];
    const float* c2      = (const float*)d_in[10];
    const float* P_obj   = (const float*)d_in[11];
    const float* pb_obj  = (const float*)d_in[12];
    const float* P_pred  = (const float*)d_in[13];
    const float* pb_pred = (const float*)d_in[14];

    __half *hh, *poolh, *gh, *objh, *predh, *tach, *w1h, *w2h, *v1h, *v2h, *poh, *pph;
    float *pooledp, *countsp;
    cudaGetSymbolAddress((void**)&hh,      g_hh);
    cudaGetSymbolAddress((void**)&pooledp, g_pooled);
    cudaGetSymbolAddress((void**)&poolh,   g_poolh);
    cudaGetSymbolAddress((void**)&gh,      g_gh);
    cudaGetSymbolAddress((void**)&countsp, g_counts);
    cudaGetSymbolAddress((void**)&objh,    g_objh);
    cudaGetSymbolAddress((void**)&predh,   g_predh);
    cudaGetSymbolAddress((void**)&tach,    g_tach);
    cudaGetSymbolAddress((void**)&w1h,     g_W1h);
    cudaGetSymbolAddress((void**)&w2h,     g_W2h);
    cudaGetSymbolAddress((void**)&v1h,     g_V1h);
    cudaGetSymbolAddress((void**)&v2h,     g_V2h);
    cudaGetSymbolAddress((void**)&poh,     g_Poh);
    cudaGetSymbolAddress((void**)&pph,     g_Pph);

    cudaFuncSetAttribute(gemm_h<0>, cudaFuncAttributeMaxDynamicSharedMemorySize, SMEM_BYTES);
    cudaFuncSetAttribute(gemm_h<2>, cudaFuncAttributeMaxDynamicSharedMemorySize, SMEM_BYTES);
    cudaFuncSetAttribute(gemm_h<3>, cudaFuncAttributeMaxDynamicSharedMemorySize, SMEM_BYTES);
    cudaFuncSetAttribute(gemm_h<4>, cudaFuncAttributeMaxDynamicSharedMemorySize, SMEM_BYTES);
    cudaFuncSetAttribute(gemm_h<6>, cudaFuncAttributeMaxDynamicSharedMemorySize, SMEM_BYTES);
    cudaFuncSetAttribute(gemm_h<7>, cudaFuncAttributeMaxDynamicSharedMemorySize, SMEM_BYTES);

    float* out_obj = (float*)d_out;
    float* out_p   = (float*)d_out + (size_t)NOBJ * DIM;

    const int gMtri = (NTRI + BM - 1) / BM;   // 782
    const int gMobj = (NOBJ + BM - 1) / BM;   // 157

    // 0: convert inputs
    prep_a_kernel<<<(unsigned)((PA1 + 255) / 256), 256>>>(
        (const float4*)objv, (const float4*)predv, (uint2*)objh, (uint2*)predh);

    // 1: convert weights + zero pooled/counts
    prep_b_kernel<<<(unsigned)((PB7 + 255) / 256), 256>>>(
        (const float4*)W1, (const float4*)W2, (const float4*)V1, (const float4*)V2,
        (const float4*)P_obj, (const float4*)P_pred,
        (uint2*)w1h, (uint2*)w2h, (uint2*)v1h, (uint2*)v2h, (uint2*)poh, (uint2*)pph,
        (float4*)pooledp, (float4*)countsp);

    // 2: counts
    count_kernel<<<(NTRI + 255) / 256, 256>>>(edges, countsp);

    // 3: [T_a | T_c] = obj @ [W1a | W1c]^T  (merged, N=1024, split-B addressing)
    gemm_h<6><<<dim3(8, gMobj), NTHR, SMEM_BYTES>>>(
        objh, w1h, 1536, nullptr, tach, nullptr, NOBJ, 1024, 512,
        nullptr, nullptr, nullptr, nullptr, nullptr, nullptr, nullptr, 0);

    // 4: h = relu(pred @ W1b^T + T_a[s] + T_c[o] + b1)
    gemm_h<4><<<dim3(4, gMtri), NTHR, SMEM_BYTES>>>(
        predh, w1h + 512, 1536, b1, hh, nullptr, NTRI, 512, 512,
        edges, tach, tach + 512, nullptr, nullptr, nullptr, nullptr, 0);

    // 5: G2 (ncu -s 5 captures this): new_t = relu(h @ W2^T + b2); split -> pooled + out_p
    gemm_h<2><<<dim3(12, gMtri), NTHR, SMEM_BYTES>>>(
        hh, w2h, 512, b2, nullptr, nullptr, NTRI, 1536, 512,
        edges, nullptr, nullptr, pooledp, out_p, nullptr, nullptr, 0);

    // 6: pooled /= max(counts,1) -> half
    normalize_kernel<<<(NOBJ * DIM + 255) / 256, 256>>>(pooledp, countsp, poolh);

    // 7: G3: g = relu(pooled @ V1^T + c1) -> half
    gemm_h<0><<<dim3(4, gMobj), NTHR, SMEM_BYTES>>>(
        poolh, v1h, 512, c1, gh, nullptr, NOBJ, 512, 512,
        nullptr, nullptr, nullptr, nullptr, nullptr, nullptr, nullptr, 0);

    // 8: G4: out_obj = relu(g @ V2^T + c2) -> float
    gemm_h<3><<<dim3(4, gMobj), NTHR, SMEM_BYTES>>>(
        gh, v2h, 512, c2, nullptr, out_obj, NOBJ, 512, 512,
        nullptr, nullptr, nullptr, nullptr, nullptr, nullptr, nullptr, 0);

    // 9: G5+G6 merged: out_obj += obj@P_obj^T+pb_obj  ||  out_p += pred@P_pred^T+pb_pred
    gemm_h<7><<<dim3(4, gMobj + gMtri), NTHR, SMEM_BYTES>>>(
        objh, poh, 512, pb_obj, nullptr, out_obj, NOBJ, 512, 512,
        nullptr, predh, pph, nullptr, nullptr, pb_pred, out_p, NTRI);
}

// round 13
// speedup vs baseline: 1.0294x; 1.0294x over previous
#include <cuda_runtime.h>
#include <cuda_fp16.h>
#include <cstdint>

#define NOBJ 20000
#define NTRI 100000
#define DIM  512

// ---------------- static device scratch (allocation-free) ----------------
__device__ __half g_hh[(size_t)NTRI * DIM];
__device__ float  g_pooled[(size_t)NOBJ * DIM];
__device__ __half g_poolh[(size_t)NOBJ * DIM];
__device__ __half g_gh[(size_t)NOBJ * DIM];
__device__ float  g_counts[NOBJ];
__device__ __half g_objh[(size_t)NOBJ * DIM];
__device__ __half g_predh[(size_t)NTRI * DIM];
__device__ __half g_tach[(size_t)NOBJ * 1024];  // [T_a | T_c] merged
__device__ __half g_W1h[512 * 1536];
__device__ __half g_W2h[1536 * 512];
__device__ __half g_V1h[512 * 512];
__device__ __half g_V2h[512 * 512];
__device__ __half g_Poh[512 * 512];
__device__ __half g_Pph[512 * 512];

// ---------------- helpers ----------------
__device__ __forceinline__ uint32_t smem_u32(const void* p) {
    uint32_t a;
    asm("{ .reg .u64 t; cvta.to.shared.u64 t, %1; cvt.u32.u64 %0, t; }" : "=r"(a) : "l"(p));
    return a;
}
__device__ __forceinline__ void cp16(uint32_t sdst, const void* gsrc) {
    asm volatile("cp.async.cg.shared.global [%0], [%1], 16;" :: "r"(sdst), "l"(gsrc) : "memory");
}
__device__ __forceinline__ void cp_commit() {
    asm volatile("cp.async.commit_group;" ::: "memory");
}
__device__ __forceinline__ void ldsm4(uint32_t* r, uint32_t addr) {
    asm volatile("ldmatrix.sync.aligned.m8n8.x4.shared.b16 {%0,%1,%2,%3}, [%4];"
                 : "=r"(r[0]), "=r"(r[1]), "=r"(r[2]), "=r"(r[3]) : "r"(addr));
}
// non-volatile: lets ptxas interleave MMAs with LDSMs
__device__ __forceinline__ void mma16816(float* d, const uint32_t* a, const uint32_t* b) {
    asm("mma.sync.aligned.m16n8k16.row.col.f32.f16.f16.f32 "
        "{%0,%1,%2,%3}, {%4,%5,%6,%7}, {%8,%9}, {%0,%1,%2,%3};"
        : "+f"(d[0]), "+f"(d[1]), "+f"(d[2]), "+f"(d[3])
        : "r"(a[0]), "r"(a[1]), "r"(a[2]), "r"(a[3]), "r"(b[0]), "r"(b[1]));
}
__device__ __forceinline__ void red2(float* p, float x, float y) {
    asm volatile("red.global.add.v2.f32 [%0], {%1,%2};"
                 :: "l"(p), "f"(x), "f"(y) : "memory");
}
__device__ __forceinline__ uint2 cvt4(float4 v) {
    __half2 h0 = __floats2half2_rn(v.x, v.y);
    __half2 h1 = __floats2half2_rn(v.z, v.w);
    uint2 u;
    u.x = *reinterpret_cast<uint32_t*>(&h0);
    u.y = *reinterpret_cast<uint32_t*>(&h1);
    return u;
}

// ---------------- GEMM config: 64x128 tile, 3 CTAs/SM (24 warps/SM) ----------------
constexpr int BM = 64, BN = 128, BK = 32;    // BK in halves
constexpr int LDA = 40;                      // smem row stride (halves); 80B rows
constexpr int NSTG = 4;
constexpr int A_BYTES = BM * LDA * 2;        // 5120
constexpr int B_BYTES = BN * LDA * 2;        // 10240
constexpr int STG_BYTES = A_BYTES + B_BYTES; // 15360
constexpr int SMEM_BYTES = NSTG * STG_BYTES; // 61440 -> 3 CTAs/SM (184KB)
constexpr int NTHR = 256;                    // 8 warps, 2x4, 32x32 warp tile

// ---------------- fp16 MMA GEMM: epi(A[M,K] @ B[N,K_ldb]^T + bias) ----------------
// MODE 0: Ch = relu(v+bias) half
// MODE 2: region = colBlock>>9: 0 -> red2 pooled[s]; 1 -> outp; 2 -> red2 pooled[o]  (relu)
// MODE 3: Cf = relu(v+bias) float
// MODE 4: Ch = relu(v + bias + tah[edges[2r]*1024+c] + tch[edges[2r+1]*1024+c]) half
// MODE 6: Ch = v half (no bias/relu); split-B: col n<512 -> B+n*ldb, n>=512 -> B+(n-512)*ldb+1024
// MODE 7: two residual GEMMs row-partitioned: blockIdx.y < ceil(M/BM) -> (A,B,bias,Cf,M)
//         else -> (tah as A2, tch as B2, bias2, Cf2, M2)
template <int MODE>
__global__ void __launch_bounds__(NTHR, 3)
gemm_h(const __half* __restrict__ A, const __half* __restrict__ B, int ldb,
       const float* __restrict__ bias,
       __half* __restrict__ Ch, float* __restrict__ Cf,
       int M, int N, int K,
       const int* __restrict__ edges,
       const __half* __restrict__ tah, const __half* __restrict__ tch,
       float* __restrict__ pooled, float* __restrict__ outp,
       const float* __restrict__ bias2, float* __restrict__ Cf2, int M2)
{
    extern __shared__ __align__(16) char dynsmem[];
    const uint32_t sbase = smem_u32(dynsmem);

    const int tid = threadIdx.x;
    const int wid = tid >> 5, lane = tid & 31;
    const int wm = wid & 1;          // 2 warp rows (32 rows each)
    const int wn = wid >> 1;         // 4 warp cols (32 cols each)

    // ---- MODE 7 dual-GEMM selection ----
    const __half* AP = A;
    const __half* BP = B;
    const float*  biasP = bias;
    float*        CfP = Cf;
    int rowBlockY = blockIdx.y;
    if (MODE == 7) {
        const int blocks0 = (M + BM - 1) / BM;
        if ((int)blockIdx.y >= blocks0) {
            AP = tah; BP = tch; biasP = bias2; CfP = Cf2;
            M = M2; rowBlockY = blockIdx.y - blocks0;
        }
    }
    const int rowBlock = rowBlockY * BM;
    const int colBlock = blockIdx.x * BN;

    // ---- loader mapping ----
    // A: 64 rows x 32 halves = 4KB; 4 threads/row, 8 halves (1 cp16) each
    const int arow = tid >> 2;               // 0..63
    const int ahoff = (tid & 3) * 8;         // 0,8,16,24
    // B: 128 rows x 32 halves = 8KB; 2 threads/row, 16 halves (2 cp16) each
    const int brow = tid >> 1;               // 0..127
    const int bhoff = (tid & 1) * 16;        // 0,16

    const int gr  = rowBlock + arow;
    const int grc = gr < M ? gr : (M - 1);
    const __half* arowp = AP + (size_t)grc * K;
    const __half* browp;
    if (MODE == 6) {
        const int n = colBlock + brow;
        browp = BP + (size_t)(n & 511) * ldb + ((n >= 512) ? 1024 : 0);
    } else {
        browp = BP + (size_t)(colBlock + brow) * ldb;
    }

    const uint32_t aDst = sbase + (uint32_t)(arow * LDA + ahoff) * 2;
    const uint32_t bDst = sbase + (uint32_t)A_BYTES + (uint32_t)(brow * LDA + bhoff) * 2;

    auto load_stage = [&](int i, int buf) {
        const uint32_t so = (uint32_t)(buf * STG_BYTES);
        cp16(aDst + so, arowp + (i << 5) + ahoff);
        {
            const __half* src = browp + (i << 5) + bhoff;
            cp16(bDst + so,      src);
            cp16(bDst + so + 16, src + 8);
        }
        cp_commit();
    };

    // ---- fragment lane addressing (byte offsets within a stage) ----
    const uint32_t aFrag = sbase
        + (uint32_t)(((wm * 32 + (lane & 15)) * LDA + ((lane >> 4) << 3)) * 2);
    const uint32_t bFrag = sbase + (uint32_t)A_BYTES
        + (uint32_t)(((wn * 32 + ((lane & 7) | ((lane >> 4) << 3))) * LDA
                      + (((lane >> 3) & 1) << 3)) * 2);

    float acc[2][4][4];
#pragma unroll
    for (int i = 0; i < 2; i++)
#pragma unroll
        for (int j = 0; j < 4; j++)
#pragma unroll
            for (int q = 0; q < 4; q++) acc[i][j][q] = 0.f;

    const int nst = K >> 5;

    load_stage(0, 0);
    load_stage(1, 1);
    load_stage(2, 2);

    int buf = 0;
    for (int i = 0; i < nst; i++) {
        if (i >= nst - 2) asm volatile("cp.async.wait_group 0;" ::: "memory");
        else              asm volatile("cp.async.wait_group 2;" ::: "memory");
        __syncthreads();

        if (i + 3 < nst) {
            int nb = buf + 3; if (nb >= NSTG) nb -= NSTG;
            load_stage(i + 3, nb);
        }

        const uint32_t so = (uint32_t)(buf * STG_BYTES);
        // A-fragment streaming: B fragments resident (8 regs), A fetched per-mt
#pragma unroll
        for (int kk = 0; kk < 2; kk++) {
            uint32_t b[2][4];
            ldsm4(b[0], bFrag + so + (uint32_t)((kk * 16) * 2));
            ldsm4(b[1], bFrag + so + (uint32_t)((16 * LDA + kk * 16) * 2));
#pragma unroll
            for (int mt = 0; mt < 2; mt++) {
                uint32_t a[4];
                ldsm4(a, aFrag + so + (uint32_t)((mt * 16 * LDA + kk * 16) * 2));
#pragma unroll
                for (int nt = 0; nt < 4; nt++)
                    mma16816(acc[mt][nt], a, &b[nt >> 1][(nt & 1) * 2]);
            }
        }

        buf++; if (buf >= NSTG) buf -= NSTG;
    }

    // ---- epilogue ----
    const int region = colBlock >> 9;
#pragma unroll
    for (int mt = 0; mt < 2; mt++) {
        const int r0 = rowBlock + wm * 32 + mt * 16 + (lane >> 2);
        const int r1 = r0 + 8;
        const bool ok0 = r0 < M, ok1 = r1 < M;
        int s0 = 0, o0 = 0, s1 = 0, o1 = 0;
        if (MODE == 2) {
            if (region == 0) {
                if (ok0) s0 = edges[2 * r0];
                if (ok1) s1 = edges[2 * r1];
            } else if (region == 2) {
                if (ok0) o0 = edges[2 * r0 + 1];
                if (ok1) o1 = edges[2 * r1 + 1];
            }
        } else if (MODE == 4) {
            if (ok0) { s0 = edges[2 * r0]; o0 = edges[2 * r0 + 1]; }
            if (ok1) { s1 = edges[2 * r1]; o1 = edges[2 * r1 + 1]; }
        }
#pragma unroll
        for (int nt = 0; nt < 4; nt++) {
            const int c = colBlock + wn * 32 + nt * 8 + 2 * (lane & 3);
            float bx = 0.f, by = 0.f;
            if (MODE != 6) { bx = biasP[c]; by = biasP[c + 1]; }
            float v00 = acc[mt][nt][0] + bx, v01 = acc[mt][nt][1] + by;
            float v10 = acc[mt][nt][2] + bx, v11 = acc[mt][nt][3] + by;
            if (MODE == 0 || MODE == 2 || MODE == 3) {
                v00 = fmaxf(v00, 0.f); v01 = fmaxf(v01, 0.f);
                v10 = fmaxf(v10, 0.f); v11 = fmaxf(v11, 0.f);
            }
            if (MODE == 0 || MODE == 6) {
                if (ok0) *reinterpret_cast<__half2*>(Ch + (size_t)r0 * N + c) = __floats2half2_rn(v00, v01);
                if (ok1) *reinterpret_cast<__half2*>(Ch + (size_t)r1 * N + c) = __floats2half2_rn(v10, v11);
            } else if (MODE == 4) {
                if (ok0) {
                    __half2 ta = *reinterpret_cast<const __half2*>(tah + (size_t)s0 * 1024 + c);
                    __half2 tc = *reinterpret_cast<const __half2*>(tch + (size_t)o0 * 1024 + c);
                    float w0 = fmaxf(v00 + __low2float(ta) + __low2float(tc), 0.f);
                    float w1 = fmaxf(v01 + __high2float(ta) + __high2float(tc), 0.f);
                    *reinterpret_cast<__half2*>(Ch + (size_t)r0 * N + c) = __floats2half2_rn(w0, w1);
                }
                if (ok1) {
                    __half2 ta = *reinterpret_cast<const __half2*>(tah + (size_t)s1 * 1024 + c);
                    __half2 tc = *reinterpret_cast<const __half2*>(tch + (size_t)o1 * 1024 + c);
                    float w0 = fmaxf(v10 + __low2float(ta) + __low2float(tc), 0.f);
                    float w1 = fmaxf(v11 + __high2float(ta) + __high2float(tc), 0.f);
                    *reinterpret_cast<__half2*>(Ch + (size_t)r1 * N + c) = __floats2half2_rn(w0, w1);
                }
            } else if (MODE == 3) {
                if (ok0) *reinterpret_cast<float2*>(Cf + (size_t)r0 * N + c) = make_float2(v00, v01);
                if (ok1) *reinterpret_cast<float2*>(Cf + (size_t)r1 * N + c) = make_float2(v10, v11);
            } else if (MODE == 7) {
                if (ok0) {
                    float2 o = *reinterpret_cast<const float2*>(CfP + (size_t)r0 * N + c);
                    *reinterpret_cast<float2*>(CfP + (size_t)r0 * N + c) = make_float2(o.x + v00, o.y + v01);
                }
                if (ok1) {
                    float2 o = *reinterpret_cast<const float2*>(CfP + (size_t)r1 * N + c);
                    *reinterpret_cast<float2*>(CfP + (size_t)r1 * N + c) = make_float2(o.x + v10, o.y + v11);
                }
            } else { // MODE 2
                const int cl = c & 511;
                if (region == 1) {
                    if (ok0) *reinterpret_cast<float2*>(outp + (size_t)r0 * DIM + cl) = make_float2(v00, v01);
                    if (ok1) *reinterpret_cast<float2*>(outp + (size_t)r1 * DIM + cl) = make_float2(v10, v11);
                } else if (region == 0) {
                    if (ok0) red2(&pooled[(size_t)s0 * DIM + cl], v00, v01);
                    if (ok1) red2(&pooled[(size_t)s1 * DIM + cl], v10, v11);
                } else {
                    if (ok0) red2(&pooled[(size_t)o0 * DIM + cl], v00, v01);
                    if (ok1) red2(&pooled[(size_t)o1 * DIM + cl], v10, v11);
                }
            }
        }
    }
}

// ---------------- merged prep kernels ----------------
constexpr size_t PA0 = 2560000;            // obj f4 count
constexpr size_t PA1 = PA0 + 12800000;     // + pred f4
__global__ void prep_a_kernel(const float4* __restrict__ objv, const float4* __restrict__ predv,
                              uint2* __restrict__ objh, uint2* __restrict__ predh)
{
    size_t i = (size_t)blockIdx.x * blockDim.x + threadIdx.x;
    if (i < PA0)      objh[i] = cvt4(objv[i]);
    else if (i < PA1) predh[i - PA0] = cvt4(predv[i - PA0]);
}

constexpr size_t PB0 = 196608;             // W1 f4
constexpr size_t PB1 = PB0 + 196608;       // W2
constexpr size_t PB2 = PB1 + 65536;        // V1
constexpr size_t PB3 = PB2 + 65536;        // V2
constexpr size_t PB4 = PB3 + 65536;        // Po
constexpr size_t PB5 = PB4 + 65536;        // Pp
constexpr size_t PB6 = PB5 + 2560000;      // zero pooled (f4)
constexpr size_t PB7 = PB6 + 5000;         // zero counts (f4)
__global__ void prep_b_kernel(const float4* __restrict__ W1, const float4* __restrict__ W2,
                              const float4* __restrict__ V1, const float4* __restrict__ V2,
                              const float4* __restrict__ Po, const float4* __restrict__ Pp,
                              uint2* __restrict__ w1h, uint2* __restrict__ w2h,
                              uint2* __restrict__ v1h, uint2* __restrict__ v2h,
                              uint2* __restrict__ poh, uint2* __restrict__ pph,
                              float4* __restrict__ pooled, float4* __restrict__ counts)
{
    size_t i = (size_t)blockIdx.x * blockDim.x + threadIdx.x;
    if (i < PB0)      w1h[i] = cvt4(W1[i]);
    else if (i < PB1) w2h[i - PB0] = cvt4(W2[i - PB0]);
    else if (i < PB2) v1h[i - PB1] = cvt4(V1[i - PB1]);
    else if (i < PB3) v2h[i - PB2] = cvt4(V2[i - PB2]);
    else if (i < PB4) poh[i - PB3] = cvt4(Po[i - PB3]);
    else if (i < PB5) pph[i - PB4] = cvt4(Pp[i - PB4]);
    else if (i < PB6) pooled[i - PB5] = make_float4(0.f, 0.f, 0.f, 0.f);
    else if (i < PB7) counts[i - PB6] = make_float4(0.f, 0.f, 0.f, 0.f);
}

__global__ void count_kernel(const int* __restrict__ edges, float* counts) {
    int i = blockIdx.x * blockDim.x + threadIdx.x;
    if (i < NTRI) {
        atomicAdd(&counts[edges[2 * i]], 1.f);
        atomicAdd(&counts[edges[2 * i + 1]], 1.f);
    }
}

__global__ void normalize_kernel(const float* __restrict__ pooled,
                                 const float* __restrict__ counts,
                                 __half* __restrict__ poolh) {
    int i = blockIdx.x * blockDim.x + threadIdx.x;
    if (i < NOBJ * DIM) {
        float c = counts[i >> 9];
        poolh[i] = __float2half_rn(pooled[i] * (1.f / fmaxf(c, 1.f)));
    }
}

// ---------------- launcher ----------------
extern "C" void kernel_launch(void* const* d_in, const int* in_sizes, int n_in,
                              void* d_out, int out_size)
{
    const float* objv    = (const float*)d_in[0];
    const float* predv   = (const float*)d_in[1];
    const int*   edges   = (const int*)  d_in[2];
    const float* W1      = (const float*)d_in[3];
    const float* b1      = (const float*)d_in[4];
    const float* W2      = (const float*)d_in[5];
    const float* b2      = (const float*)d_in[6];
    const float* V1      = (const float*)d_in[7];
    const float* c1      = (const float*)d_in[8];
    const float* V2      = (const float*)d_in[9];
    const float* c2      = (const float*)d_in[10];
    const float* P_obj   = (const float*)d_in[11];
    const float* pb_obj  = (const float*)d_in[12];
    const float* P_pred  = (const float*)d_in[13];
    const float* pb_pred = (const float*)d_in[14];

    __half *hh, *poolh, *gh, *objh, *predh, *tach, *w1h, *w2h, *v1h, *v2h, *poh, *pph;
    float *pooledp, *countsp;
    cudaGetSymbolAddress((void**)&hh,      g_hh);
    cudaGetSymbolAddress((void**)&pooledp, g_pooled);
    cudaGetSymbolAddress((void**)&poolh,   g_poolh);
    cudaGetSymbolAddress((void**)&gh,      g_gh);
    cudaGetSymbolAddress((void**)&countsp, g_counts);
    cudaGetSymbolAddress((void**)&objh,    g_objh);
    cudaGetSymbolAddress((void**)&predh,   g_predh);
    cudaGetSymbolAddress((void**)&tach,    g_tach);
    cudaGetSymbolAddress((void**)&w1h,     g_W1h);
    cudaGetSymbolAddress((void**)&w2h,     g_W2h);
    cudaGetSymbolAddress((void**)&v1h,     g_V1h);
    cudaGetSymbolAddress((void**)&v2h,     g_V2h);
    cudaGetSymbolAddress((void**)&poh,     g_Poh);
    cudaGetSymbolAddress((void**)&pph,     g_Pph);

    cudaFuncSetAttribute(gemm_h<0>, cudaFuncAttributeMaxDynamicSharedMemorySize, SMEM_BYTES);
    cudaFuncSetAttribute(gemm_h<2>, cudaFuncAttributeMaxDynamicSharedMemorySize, SMEM_BYTES);
    cudaFuncSetAttribute(gemm_h<3>, cudaFuncAttributeMaxDynamicSharedMemorySize, SMEM_BYTES);
    cudaFuncSetAttribute(gemm_h<4>, cudaFuncAttributeMaxDynamicSharedMemorySize, SMEM_BYTES);
    cudaFuncSetAttribute(gemm_h<6>, cudaFuncAttributeMaxDynamicSharedMemorySize, SMEM_BYTES);
    cudaFuncSetAttribute(gemm_h<7>, cudaFuncAttributeMaxDynamicSharedMemorySize, SMEM_BYTES);

    float* out_obj = (float*)d_out;
    float* out_p   = (float*)d_out + (size_t)NOBJ * DIM;

    const int gMtri = (NTRI + BM - 1) / BM;   // 1563
    const int gMobj = (NOBJ + BM - 1) / BM;   // 313

    // 0: convert inputs
    prep_a_kernel<<<(unsigned)((PA1 + 255) / 256), 256>>>(
        (const float4*)objv, (const float4*)predv, (uint2*)objh, (uint2*)predh);

    // 1: convert weights + zero pooled/counts
    prep_b_kernel<<<(unsigned)((PB7 + 255) / 256), 256>>>(
        (const float4*)W1, (const float4*)W2, (const float4*)V1, (const float4*)V2,
        (const float4*)P_obj, (const float4*)P_pred,
        (uint2*)w1h, (uint2*)w2h, (uint2*)v1h, (uint2*)v2h, (uint2*)poh, (uint2*)pph,
        (float4*)pooledp, (float4*)countsp);

    // 2: counts
    count_kernel<<<(NTRI + 255) / 256, 256>>>(edges, countsp);

    // 3: [T_a | T_c] = obj @ [W1a | W1c]^T  (merged, N=1024, split-B addressing)
    gemm_h<6><<<dim3(8, gMobj), NTHR, SMEM_BYTES>>>(
        objh, w1h, 1536, nullptr, tach, nullptr, NOBJ, 1024, 512,
        nullptr, nullptr, nullptr, nullptr, nullptr, nullptr, nullptr, 0);

    // 4: h = relu(pred @ W1b^T + T_a[s] + T_c[o] + b1)
    gemm_h<4><<<dim3(4, gMtri), NTHR, SMEM_BYTES>>>(
        predh, w1h + 512, 1536, b1, hh, nullptr, NTRI, 512, 512,
        edges, tach, tach + 512, nullptr, nullptr, nullptr, nullptr, 0);

    // 5: G2 (ncu -s 5 captures this): new_t = relu(h @ W2^T + b2); split -> pooled + out_p
    gemm_h<2><<<dim3(12, gMtri), NTHR, SMEM_BYTES>>>(
        hh, w2h, 512, b2, nullptr, nullptr, NTRI, 1536, 512,
        edges, nullptr, nullptr, pooledp, out_p, nullptr, nullptr, 0);

    // 6: pooled /= max(counts,1) -> half
    normalize_kernel<<<(NOBJ * DIM + 255) / 256, 256>>>(pooledp, countsp, poolh);

    // 7: G3: g = relu(pooled @ V1^T + c1) -> half
    gemm_h<0><<<dim3(4, gMobj), NTHR, SMEM_BYTES>>>(
        poolh, v1h, 512, c1, gh, nullptr, NOBJ, 512, 512,
        nullptr, nullptr, nullptr, nullptr, nullptr, nullptr, nullptr, 0);

    // 8: G4: out_obj = relu(g @ V2^T + c2) -> float
    gemm_h<3><<<dim3(4, gMobj), NTHR, SMEM_BYTES>>>(
        gh, v2h, 512, c2, nullptr, out_obj, NOBJ, 512, 512,
        nullptr, nullptr, nullptr, nullptr, nullptr, nullptr, nullptr, 0);

    // 9: G5+G6 merged: out_obj += obj@P_obj^T+pb_obj  ||  out_p += pred@P_pred^T+pb_pred
    gemm_h<7><<<dim3(4, gMobj + gMtri), NTHR, SMEM_BYTES>>>(
        objh, poh, 512, pb_obj, nullptr, out_obj, NOBJ, 512, 512,
        nullptr, predh, pph, nullptr, nullptr, pb_pred, out_p, NTRI);
}

// round 14
// speedup vs baseline: 1.0897x; 1.0585x over previous
#include <cuda_runtime.h>
#include <cuda_fp16.h>
#include <cstdint>

#define NOBJ 20000
#define NTRI 100000
#define DIM  512

// ---------------- static device scratch (allocation-free) ----------------
__device__ __half g_hh[(size_t)NTRI * DIM];
__device__ float  g_pooled[(size_t)NOBJ * DIM];
__device__ __half g_poolh[(size_t)NOBJ * DIM];
__device__ __half g_gh[(size_t)NOBJ * DIM];
__device__ float  g_counts[NOBJ];
__device__ __half g_objh[(size_t)NOBJ * DIM];
__device__ __half g_predh[(size_t)NTRI * DIM];
__device__ __half g_tach[(size_t)NOBJ * 1024];  // [T_a | T_c] merged
__device__ __half g_W1h[512 * 1536];
__device__ __half g_W2h[1536 * 512];
__device__ __half g_V1h[512 * 512];
__device__ __half g_V2h[512 * 512];
__device__ __half g_Poh[512 * 512];
__device__ __half g_Pph[512 * 512];

// ---------------- helpers ----------------
__device__ __forceinline__ uint32_t smem_u32(const void* p) {
    uint32_t a;
    asm("{ .reg .u64 t; cvta.to.shared.u64 t, %1; cvt.u32.u64 %0, t; }" : "=r"(a) : "l"(p));
    return a;
}
__device__ __forceinline__ void cp16(uint32_t sdst, const void* gsrc) {
    asm volatile("cp.async.cg.shared.global [%0], [%1], 16;" :: "r"(sdst), "l"(gsrc) : "memory");
}
__device__ __forceinline__ void cp_commit() {
    asm volatile("cp.async.commit_group;" ::: "memory");
}
__device__ __forceinline__ void ldsm4(uint32_t* r, uint32_t addr) {
    asm volatile("ldmatrix.sync.aligned.m8n8.x4.shared.b16 {%0,%1,%2,%3}, [%4];"
                 : "=r"(r[0]), "=r"(r[1]), "=r"(r[2]), "=r"(r[3]) : "r"(addr));
}
// non-volatile: lets ptxas interleave MMAs with LDSMs
__device__ __forceinline__ void mma16816(float* d, const uint32_t* a, const uint32_t* b) {
    asm("mma.sync.aligned.m16n8k16.row.col.f32.f16.f16.f32 "
        "{%0,%1,%2,%3}, {%4,%5,%6,%7}, {%8,%9}, {%0,%1,%2,%3};"
        : "+f"(d[0]), "+f"(d[1]), "+f"(d[2]), "+f"(d[3])
        : "r"(a[0]), "r"(a[1]), "r"(a[2]), "r"(a[3]), "r"(b[0]), "r"(b[1]));
}
__device__ __forceinline__ void red2(float* p, float x, float y) {
    asm volatile("red.global.add.v2.f32 [%0], {%1,%2};"
                 :: "l"(p), "f"(x), "f"(y) : "memory");
}
__device__ __forceinline__ uint2 cvt4(float4 v) {
    __half2 h0 = __floats2half2_rn(v.x, v.y);
    __half2 h1 = __floats2half2_rn(v.z, v.w);
    uint2 u;
    u.x = *reinterpret_cast<uint32_t*>(&h0);
    u.y = *reinterpret_cast<uint32_t*>(&h1);
    return u;
}

// ---------------- GEMM config (round-11 best: 128x128, BK=32, 4 stages, 2 CTAs/SM) ----------------
constexpr int BM = 128, BN = 128, BK = 32;   // BK in halves
constexpr int LDA = 40;                      // smem row stride (halves); 80B rows
constexpr int NSTG = 4;
constexpr int A_BYTES = BM * LDA * 2;        // 10240
constexpr int B_BYTES = BN * LDA * 2;        // 10240
constexpr int STG_BYTES = A_BYTES + B_BYTES; // 20480
constexpr int SMEM_BYTES = NSTG * STG_BYTES; // 81920 -> 2 CTAs/SM
constexpr int NTHR = 256;                    // 8 warps, 2x4, 64x32 warp tile

// ---------------- fp16 MMA GEMM: epi(A[M,K] @ B[N,K_ldb]^T + bias) ----------------
// MODE 0: Ch = relu(v+bias) half
// MODE 2: region = colBlock>>9: 0 -> red2 pooled[s]; 1 -> outp; 2 -> red2 pooled[o]  (relu)
// MODE 3: Cf = relu(v+bias) float
// MODE 4: Ch = relu(v + bias + tah[edges[2r]*1024+c] + tch[edges[2r+1]*1024+c]) half
// MODE 6: Ch = v half (no bias/relu); split-B: col n<512 -> B+n*ldb, n>=512 -> B+(n-512)*ldb+1024
// MODE 7: two residual GEMMs row-partitioned: blockIdx.y < ceil(M/128) -> (A,B,bias,Cf,M)
//         else -> (tah as A2, tch as B2, bias2, Cf2, M2)
template <int MODE>
__global__ void __launch_bounds__(NTHR, 2)
gemm_h(const __half* __restrict__ A, const __half* __restrict__ B, int ldb,
       const float* __restrict__ bias,
       __half* __restrict__ Ch, float* __restrict__ Cf,
       int M, int N, int K,
       const int* __restrict__ edges,
       const __half* __restrict__ tah, const __half* __restrict__ tch,
       float* __restrict__ pooled, float* __restrict__ outp,
       const float* __restrict__ bias2, float* __restrict__ Cf2, int M2)
{
    extern __shared__ __align__(16) char dynsmem[];
    const uint32_t sbase = smem_u32(dynsmem);

    const int tid = threadIdx.x;
    const int wid = tid >> 5, lane = tid & 31;
    const int wm = wid & 1;          // 2 warp rows (64 rows each)
    const int wn = wid >> 1;         // 4 warp cols (32 cols each)

    // ---- MODE 7 dual-GEMM selection ----
    const __half* AP = A;
    const __half* BP = B;
    const float*  biasP = bias;
    float*        CfP = Cf;
    int rowBlockY = blockIdx.y;
    if (MODE == 7) {
        const int blocks0 = (M + BM - 1) >> 7;
        if ((int)blockIdx.y >= blocks0) {
            AP = tah; BP = tch; biasP = bias2; CfP = Cf2;
            M = M2; rowBlockY = blockIdx.y - blocks0;
        }
    }
    const int rowBlock = rowBlockY * BM;
    const int colBlock = blockIdx.x * BN;

    // ---- loader mapping: 2 threads per row, 16 halves each ----
    const int lrow = tid >> 1;               // 0..127
    const int lhs  = (tid & 1) * 16;         // halves
    const int gr  = rowBlock + lrow;
    const int grc = gr < M ? gr : (M - 1);
    const __half* arowp = AP + (size_t)grc * K;
    const __half* browp;
    if (MODE == 6) {
        const int n = colBlock + lrow;
        browp = BP + (size_t)(n & 511) * ldb + ((n >= 512) ? 1024 : 0);
    } else {
        browp = BP + (size_t)(colBlock + lrow) * ldb;
    }

    const uint32_t aDst = sbase + (uint32_t)(lrow * LDA + lhs) * 2;
    const uint32_t bDst = sbase + (uint32_t)A_BYTES + (uint32_t)(lrow * LDA + lhs) * 2;

    auto load_stage = [&](int i, int buf) {
        const uint32_t so = (uint32_t)(buf * STG_BYTES);
        const int kb = (i << 5) + lhs;
        {
            const __half* src = arowp + kb;
            cp16(aDst + so,      src);
            cp16(aDst + so + 16, src + 8);
        }
        {
            const __half* src = browp + kb;
            cp16(bDst + so,      src);
            cp16(bDst + so + 16, src + 8);
        }
        cp_commit();
    };

    // ---- fragment lane addressing (byte offsets within a stage) ----
    const uint32_t aFrag = sbase
        + (uint32_t)(((wm * 64 + (lane & 15)) * LDA + ((lane >> 4) << 3)) * 2);
    const uint32_t bFrag = sbase + (uint32_t)A_BYTES
        + (uint32_t)(((wn * 32 + ((lane & 7) | ((lane >> 4) << 3))) * LDA
                      + (((lane >> 3) & 1) << 3)) * 2);

    float acc[4][4][4];
#pragma unroll
    for (int i = 0; i < 4; i++)
#pragma unroll
        for (int j = 0; j < 4; j++)
#pragma unroll
            for (int q = 0; q < 4; q++) acc[i][j][q] = 0.f;

    const int nst = K >> 5;

    load_stage(0, 0);
    load_stage(1, 1);
    load_stage(2, 2);

    int buf = 0;
    for (int i = 0; i < nst; i++) {
        if (i >= nst - 2) asm volatile("cp.async.wait_group 0;" ::: "memory");
        else              asm volatile("cp.async.wait_group 2;" ::: "memory");
        __syncthreads();

        if (i + 3 < nst) {
            int nb = buf + 3; if (nb >= NSTG) nb -= NSTG;
            load_stage(i + 3, nb);
        }

        const uint32_t so = (uint32_t)(buf * STG_BYTES);
        // A-fragment streaming: B fragments resident (8 regs), A fetched per-mt
#pragma unroll
        for (int kk = 0; kk < 2; kk++) {
            uint32_t b[2][4];
            ldsm4(b[0], bFrag + so + (uint32_t)((kk * 16) * 2));
            ldsm4(b[1], bFrag + so + (uint32_t)((16 * LDA + kk * 16) * 2));
#pragma unroll
            for (int mt = 0; mt < 4; mt++) {
                uint32_t a[4];
                ldsm4(a, aFrag + so + (uint32_t)((mt * 16 * LDA + kk * 16) * 2));
#pragma unroll
                for (int nt = 0; nt < 4; nt++)
                    mma16816(acc[mt][nt], a, &b[nt >> 1][(nt & 1) * 2]);
            }
        }

        buf++; if (buf >= NSTG) buf -= NSTG;
    }

    // ---- epilogue ----
    const int region = colBlock >> 9;
#pragma unroll
    for (int mt = 0; mt < 4; mt++) {
        const int r0 = rowBlock + wm * 64 + mt * 16 + (lane >> 2);
        const int r1 = r0 + 8;
        const bool ok0 = r0 < M, ok1 = r1 < M;
        int s0 = 0, o0 = 0, s1 = 0, o1 = 0;
        if (MODE == 2) {
            if (region == 0) {
                if (ok0) s0 = edges[2 * r0];
                if (ok1) s1 = edges[2 * r1];
            } else if (region == 2) {
                if (ok0) o0 = edges[2 * r0 + 1];
                if (ok1) o1 = edges[2 * r1 + 1];
            }
        } else if (MODE == 4) {
            if (ok0) { s0 = edges[2 * r0]; o0 = edges[2 * r0 + 1]; }
            if (ok1) { s1 = edges[2 * r1]; o1 = edges[2 * r1 + 1]; }
        }
#pragma unroll
        for (int nt = 0; nt < 4; nt++) {
            const int c = colBlock + wn * 32 + nt * 8 + 2 * (lane & 3);
            float bx = 0.f, by = 0.f;
            if (MODE != 6) { bx = biasP[c]; by = biasP[c + 1]; }
            float v00 = acc[mt][nt][0] + bx, v01 = acc[mt][nt][1] + by;
            float v10 = acc[mt][nt][2] + bx, v11 = acc[mt][nt][3] + by;
            if (MODE == 0 || MODE == 2 || MODE == 3) {
                v00 = fmaxf(v00, 0.f); v01 = fmaxf(v01, 0.f);
                v10 = fmaxf(v10, 0.f); v11 = fmaxf(v11, 0.f);
            }
            if (MODE == 0 || MODE == 6) {
                if (ok0) *reinterpret_cast<__half2*>(Ch + (size_t)r0 * N + c) = __floats2half2_rn(v00, v01);
                if (ok1) *reinterpret_cast<__half2*>(Ch + (size_t)r1 * N + c) = __floats2half2_rn(v10, v11);
            } else if (MODE == 4) {
                if (ok0) {
                    __half2 ta = *reinterpret_cast<const __half2*>(tah + (size_t)s0 * 1024 + c);
                    __half2 tc = *reinterpret_cast<const __half2*>(tch + (size_t)o0 * 1024 + c);
                    float w0 = fmaxf(v00 + __low2float(ta) + __low2float(tc), 0.f);
                    float w1 = fmaxf(v01 + __high2float(ta) + __high2float(tc), 0.f);
                    *reinterpret_cast<__half2*>(Ch + (size_t)r0 * N + c) = __floats2half2_rn(w0, w1);
                }
                if (ok1) {
                    __half2 ta = *reinterpret_cast<const __half2*>(tah + (size_t)s1 * 1024 + c);
                    __half2 tc = *reinterpret_cast<const __half2*>(tch + (size_t)o1 * 1024 + c);
                    float w0 = fmaxf(v10 + __low2float(ta) + __low2float(tc), 0.f);
                    float w1 = fmaxf(v11 + __high2float(ta) + __high2float(tc), 0.f);
                    *reinterpret_cast<__half2*>(Ch + (size_t)r1 * N + c) = __floats2half2_rn(w0, w1);
                }
            } else if (MODE == 3) {
                if (ok0) *reinterpret_cast<float2*>(Cf + (size_t)r0 * N + c) = make_float2(v00, v01);
                if (ok1) *reinterpret_cast<float2*>(Cf + (size_t)r1 * N + c) = make_float2(v10, v11);
            } else if (MODE == 7) {
                if (ok0) {
                    float2 o = *reinterpret_cast<const float2*>(CfP + (size_t)r0 * N + c);
                    *reinterpret_cast<float2*>(CfP + (size_t)r0 * N + c) = make_float2(o.x + v00, o.y + v01);
                }
                if (ok1) {
                    float2 o = *reinterpret_cast<const float2*>(CfP + (size_t)r1 * N + c);
                    *reinterpret_cast<float2*>(CfP + (size_t)r1 * N + c) = make_float2(o.x + v10, o.y + v11);
                }
            } else { // MODE 2
                const int cl = c & 511;
                if (region == 1) {
                    if (ok0) *reinterpret_cast<float2*>(outp + (size_t)r0 * DIM + cl) = make_float2(v00, v01);
                    if (ok1) *reinterpret_cast<float2*>(outp + (size_t)r1 * DIM + cl) = make_float2(v10, v11);
                } else if (region == 0) {
                    if (ok0) red2(&pooled[(size_t)s0 * DIM + cl], v00, v01);
                    if (ok1) red2(&pooled[(size_t)s1 * DIM + cl], v10, v11);
                } else {
                    if (ok0) red2(&pooled[(size_t)o0 * DIM + cl], v00, v01);
                    if (ok1) red2(&pooled[(size_t)o1 * DIM + cl], v10, v11);
                }
            }
        }
    }
}

// ---------------- merged prep kernels ----------------
constexpr size_t PA0 = 2560000;            // obj f4 count
constexpr size_t PA1 = PA0 + 12800000;     // + pred f4
__global__ void prep_a_kernel(const float4* __restrict__ objv, const float4* __restrict__ predv,
                              uint2* __restrict__ objh, uint2* __restrict__ predh)
{
    size_t i = (size_t)blockIdx.x * blockDim.x + threadIdx.x;
    if (i < PA0)      objh[i] = cvt4(objv[i]);
    else if (i < PA1) predh[i - PA0] = cvt4(predv[i - PA0]);
}

// prep_b: f2h of weights + zero pooled/counts + edge counting (fused)
constexpr size_t PB0 = 196608;             // W1 f4
constexpr size_t PB1 = PB0 + 196608;       // W2
constexpr size_t PB2 = PB1 + 65536;        // V1
constexpr size_t PB3 = PB2 + 65536;        // V2
constexpr size_t PB4 = PB3 + 65536;        // Po
constexpr size_t PB5 = PB4 + 65536;        // Pp
constexpr size_t PB6 = PB5 + 2560000;      // zero pooled (f4)
constexpr size_t PB7 = PB6 + 5000;         // zero counts (f4)
constexpr size_t PB8 = PB7 + NTRI;         // count edges (NOTE: counts zeroed before
                                           // any count thread runs? NO — must split.)
__global__ void prep_b_kernel(const float4* __restrict__ W1, const float4* __restrict__ W2,
                              const float4* __restrict__ V1, const float4* __restrict__ V2,
                              const float4* __restrict__ Po, const float4* __restrict__ Pp,
                              uint2* __restrict__ w1h, uint2* __restrict__ w2h,
                              uint2* __restrict__ v1h, uint2* __restrict__ v2h,
                              uint2* __restrict__ poh, uint2* __restrict__ pph,
                              float4* __restrict__ pooled, float4* __restrict__ counts)
{
    size_t i = (size_t)blockIdx.x * blockDim.x + threadIdx.x;
    if (i < PB0)      w1h[i] = cvt4(W1[i]);
    else if (i < PB1) w2h[i - PB0] = cvt4(W2[i - PB0]);
    else if (i < PB2) v1h[i - PB1] = cvt4(V1[i - PB1]);
    else if (i < PB3) v2h[i - PB2] = cvt4(V2[i - PB2]);
    else if (i < PB4) poh[i - PB3] = cvt4(Po[i - PB3]);
    else if (i < PB5) pph[i - PB4] = cvt4(Pp[i - PB4]);
    else if (i < PB6) pooled[i - PB5] = make_float4(0.f, 0.f, 0.f, 0.f);
    else if (i < PB7) counts[i - PB6] = make_float4(0.f, 0.f, 0.f, 0.f);
}

// count kept separate (counts must be fully zeroed first — grid-wide ordering
// inside one kernel is not guaranteed)
__global__ void count_kernel(const int* __restrict__ edges, float* counts) {
    int i = blockIdx.x * blockDim.x + threadIdx.x;
    if (i < NTRI) {
        atomicAdd(&counts[edges[2 * i]], 1.f);
        atomicAdd(&counts[edges[2 * i + 1]], 1.f);
    }
}

__global__ void normalize_kernel(const float* __restrict__ pooled,
                                 const float* __restrict__ counts,
                                 __half* __restrict__ poolh) {
    int i = blockIdx.x * blockDim.x + threadIdx.x;
    if (i < NOBJ * DIM) {
        float c = counts[i >> 9];
        poolh[i] = __float2half_rn(pooled[i] * (1.f / fmaxf(c, 1.f)));
    }
}

// ---------------- launcher ----------------
extern "C" void kernel_launch(void* const* d_in, const int* in_sizes, int n_in,
                              void* d_out, int out_size)
{
    const float* objv    = (const float*)d_in[0];
    const float* predv   = (const float*)d_in[1];
    const int*   edges   = (const int*)  d_in[2];
    const float* W1      = (const float*)d_in[3];
    const float* b1      = (const float*)d_in[4];
    const float* W2      = (const float*)d_in[5];
    const float* b2      = (const float*)d_in[6];
    const float* V1      = (const float*)d_in[7];
    const float* c1      = (const float*)d_in[8];
    const float* V2      = (const float*)d_in[9];
    const float* c2      = (const float*)d_in[10];
    const float* P_obj   = (const float*)d_in[11];
    const float* pb_obj  = (const float*)d_in[12];
    const float* P_pred  = (const float*)d_in[13];
    const float* pb_pred = (const float*)d_in[14];

    __half *hh, *poolh, *gh, *objh, *predh, *tach, *w1h, *w2h, *v1h, *v2h, *poh, *pph;
    float *pooledp, *countsp;
    cudaGetSymbolAddress((void**)&hh,      g_hh);
    cudaGetSymbolAddress((void**)&pooledp, g_pooled);
    cudaGetSymbolAddress((void**)&poolh,   g_poolh);
    cudaGetSymbolAddress((void**)&gh,      g_gh);
    cudaGetSymbolAddress((void**)&countsp, g_counts);
    cudaGetSymbolAddress((void**)&objh,    g_objh);
    cudaGetSymbolAddress((void**)&predh,   g_predh);
    cudaGetSymbolAddress((void**)&tach,    g_tach);
    cudaGetSymbolAddress((void**)&w1h,     g_W1h);
    cudaGetSymbolAddress((void**)&w2h,     g_W2h);
    cudaGetSymbolAddress((void**)&v1h,     g_V1h);
    cudaGetSymbolAddress((void**)&v2h,     g_V2h);
    cudaGetSymbolAddress((void**)&poh,     g_Poh);
    cudaGetSymbolAddress((void**)&pph,     g_Pph);

    cudaFuncSetAttribute(gemm_h<0>, cudaFuncAttributeMaxDynamicSharedMemorySize, SMEM_BYTES);
    cudaFuncSetAttribute(gemm_h<2>, cudaFuncAttributeMaxDynamicSharedMemorySize, SMEM_BYTES);
    cudaFuncSetAttribute(gemm_h<3>, cudaFuncAttributeMaxDynamicSharedMemorySize, SMEM_BYTES);
    cudaFuncSetAttribute(gemm_h<4>, cudaFuncAttributeMaxDynamicSharedMemorySize, SMEM_BYTES);
    cudaFuncSetAttribute(gemm_h<6>, cudaFuncAttributeMaxDynamicSharedMemorySize, SMEM_BYTES);
    cudaFuncSetAttribute(gemm_h<7>, cudaFuncAttributeMaxDynamicSharedMemorySize, SMEM_BYTES);

    float* out_obj = (float*)d_out;
    float* out_p   = (float*)d_out + (size_t)NOBJ * DIM;

    const int gMtri = (NTRI + BM - 1) / BM;   // 782
    const int gMobj = (NOBJ + BM - 1) / BM;   // 157

    // 0: convert inputs
    prep_a_kernel<<<(unsigned)((PA1 + 255) / 256), 256>>>(
        (const float4*)objv, (const float4*)predv, (uint2*)objh, (uint2*)predh);

    // 1: convert weights + zero pooled/counts
    prep_b_kernel<<<(unsigned)((PB7 + 255) / 256), 256>>>(
        (const float4*)W1, (const float4*)W2, (const float4*)V1, (const float4*)V2,
        (const float4*)P_obj, (const float4*)P_pred,
        (uint2*)w1h, (uint2*)w2h, (uint2*)v1h, (uint2*)v2h, (uint2*)poh, (uint2*)pph,
        (float4*)pooledp, (float4*)countsp);

    // 2: counts (after counts zeroed by prep_b)
    count_kernel<<<(NTRI + 255) / 256, 256>>>(edges, countsp);

    // 3: [T_a | T_c] = obj @ [W1a | W1c]^T  (merged, N=1024, split-B addressing)
    gemm_h<6><<<dim3(8, gMobj), NTHR, SMEM_BYTES>>>(
        objh, w1h, 1536, nullptr, tach, nullptr, NOBJ, 1024, 512,
        nullptr, nullptr, nullptr, nullptr, nullptr, nullptr, nullptr, 0);

    // 4: h = relu(pred @ W1b^T + T_a[s] + T_c[o] + b1)
    gemm_h<4><<<dim3(4, gMtri), NTHR, SMEM_BYTES>>>(
        predh, w1h + 512, 1536, b1, hh, nullptr, NTRI, 512, 512,
        edges, tach, tach + 512, nullptr, nullptr, nullptr, nullptr, 0);

    // 5: G2: new_t = relu(h @ W2^T + b2); split -> pooled reds + out_p
    gemm_h<2><<<dim3(12, gMtri), NTHR, SMEM_BYTES>>>(
        hh, w2h, 512, b2, nullptr, nullptr, NTRI, 1536, 512,
        edges, nullptr, nullptr, pooledp, out_p, nullptr, nullptr, 0);

    // 6: pooled /= max(counts,1) -> half
    normalize_kernel<<<(NOBJ * DIM + 255) / 256, 256>>>(pooledp, countsp, poolh);

    // 7: G3: g = relu(pooled @ V1^T + c1) -> half
    gemm_h<0><<<dim3(4, gMobj), NTHR, SMEM_BYTES>>>(
        poolh, v1h, 512, c1, gh, nullptr, NOBJ, 512, 512,
        nullptr, nullptr, nullptr, nullptr, nullptr, nullptr, nullptr, 0);

    // 8: G4: out_obj = relu(g @ V2^T + c2) -> float
    gemm_h<3><<<dim3(4, gMobj), NTHR, SMEM_BYTES>>>(
        gh, v2h, 512, c2, nullptr, out_obj, NOBJ, 512, 512,
        nullptr, nullptr, nullptr, nullptr, nullptr, nullptr, nullptr, 0);

    // 9: G5+G6 merged: out_obj += obj@P_obj^T+pb_obj  ||  out_p += pred@P_pred^T+pb_pred
    gemm_h<7><<<dim3(4, gMobj + gMtri), NTHR, SMEM_BYTES>>>(
        objh, poh, 512, pb_obj, nullptr, out_obj, NOBJ, 512, 512,
        nullptr, predh, pph, nullptr, nullptr, pb_pred, out_p, NTRI);
}

// round 15
// speedup vs baseline: 1.0899x; 1.0002x over previous
#include <cuda_runtime.h>
#include <cuda_fp16.h>
#include <cstdint>

#define NOBJ 20000
#define NTRI 100000
#define DIM  512

// ---------------- static device scratch (allocation-free) ----------------
__device__ __half g_hh[(size_t)NTRI * DIM];
__device__ float  g_pooled[(size_t)NOBJ * DIM];
__device__ __half g_poolh[(size_t)NOBJ * DIM];
__device__ __half g_gh[(size_t)NOBJ * DIM];
__device__ float  g_counts[NOBJ];
__device__ __half g_objh[(size_t)NOBJ * DIM];
__device__ __half g_predh[(size_t)NTRI * DIM];
__device__ __half g_tach[(size_t)NOBJ * 1024];  // [T_a | T_c] merged
__device__ __half g_W1h[512 * 1536];
__device__ __half g_W2h[1536 * 512];
__device__ __half g_V1h[512 * 512];
__device__ __half g_V2h[512 * 512];
__device__ __half g_Poh[512 * 512];
__device__ __half g_Pph[512 * 512];

// ---------------- helpers ----------------
__device__ __forceinline__ uint32_t smem_u32(const void* p) {
    uint32_t a;
    asm("{ .reg .u64 t; cvta.to.shared.u64 t, %1; cvt.u32.u64 %0, t; }" : "=r"(a) : "l"(p));
    return a;
}
__device__ __forceinline__ void cp16(uint32_t sdst, const void* gsrc) {
    asm volatile("cp.async.cg.shared.global [%0], [%1], 16;" :: "r"(sdst), "l"(gsrc) : "memory");
}
__device__ __forceinline__ void cp_commit() {
    asm volatile("cp.async.commit_group;" ::: "memory");
}
__device__ __forceinline__ void ldsm4(uint32_t* r, uint32_t addr) {
    asm volatile("ldmatrix.sync.aligned.m8n8.x4.shared.b16 {%0,%1,%2,%3}, [%4];"
                 : "=r"(r[0]), "=r"(r[1]), "=r"(r[2]), "=r"(r[3]) : "r"(addr));
}
// non-volatile: lets ptxas interleave MMAs with LDSMs
__device__ __forceinline__ void mma16816(float* d, const uint32_t* a, const uint32_t* b) {
    asm("mma.sync.aligned.m16n8k16.row.col.f32.f16.f16.f32 "
        "{%0,%1,%2,%3}, {%4,%5,%6,%7}, {%8,%9}, {%0,%1,%2,%3};"
        : "+f"(d[0]), "+f"(d[1]), "+f"(d[2]), "+f"(d[3])
        : "r"(a[0]), "r"(a[1]), "r"(a[2]), "r"(a[3]), "r"(b[0]), "r"(b[1]));
}
__device__ __forceinline__ void red2(float* p, float x, float y) {
    asm volatile("red.global.add.v2.f32 [%0], {%1,%2};"
                 :: "l"(p), "f"(x), "f"(y) : "memory");
}
__device__ __forceinline__ uint2 cvt4(float4 v) {
    __half2 h0 = __floats2half2_rn(v.x, v.y);
    __half2 h1 = __floats2half2_rn(v.z, v.w);
    uint2 u;
    u.x = *reinterpret_cast<uint32_t*>(&h0);
    u.y = *reinterpret_cast<uint32_t*>(&h1);
    return u;
}

// ---------------- GEMM config (round-11/14 best: 128x128, BK=32, 4 stages, 2 CTAs/SM) ----------------
constexpr int BM = 128, BN = 128, BK = 32;   // BK in halves
constexpr int LDA = 40;                      // smem row stride (halves); 80B rows
constexpr int NSTG = 4;
constexpr int A_BYTES = BM * LDA * 2;        // 10240
constexpr int B_BYTES = BN * LDA * 2;        // 10240
constexpr int STG_BYTES = A_BYTES + B_BYTES; // 20480
constexpr int SMEM_BYTES = NSTG * STG_BYTES; // 81920 -> 2 CTAs/SM
constexpr int NTHR = 256;                    // 8 warps, 2x4, 64x32 warp tile

// ---------------- fp16 MMA GEMM: epi(A[M,K] @ B[N,K_ldb]^T + bias) ----------------
// MODE 0: Ch = relu(v+bias) half
// MODE 2: region = colBlock>>9: 0 -> red2 pooled[s]; 1 -> outp; 2 -> red2 pooled[o]  (relu)
// MODE 4: Ch = relu(v + bias + tah[edges[2r]*1024+c] + tch[edges[2r+1]*1024+c]) half
// MODE 6: Ch = v half (no bias/relu); split-B: col n<512 -> B+n*ldb, n>=512 -> B+(n-512)*ldb+1024
// MODE 7: two residual GEMMs row-partitioned: blockIdx.y < ceil(M/128) -> (A,B,bias,Cf,M)
//         else -> (tah as A2, tch as B2, bias2, Cf2, M2)  [Cf += v+bias]
// MODE 8: fused dual-K GEMM: phase A (A,B) K=512, then acc=relu(acc+bias[col]),
//         then phase B (tah as A2, tch as B2) K=512; store Cf = acc + bias2[col]
template <int MODE>
__global__ void __launch_bounds__(NTHR, 2)
gemm_h(const __half* __restrict__ A, const __half* __restrict__ B, int ldb,
       const float* __restrict__ bias,
       __half* __restrict__ Ch, float* __restrict__ Cf,
       int M, int N, int K,
       const int* __restrict__ edges,
       const __half* __restrict__ tah, const __half* __restrict__ tch,
       float* __restrict__ pooled, float* __restrict__ outp,
       const float* __restrict__ bias2, float* __restrict__ Cf2, int M2)
{
    extern __shared__ __align__(16) char dynsmem[];
    const uint32_t sbase = smem_u32(dynsmem);

    const int tid = threadIdx.x;
    const int wid = tid >> 5, lane = tid & 31;
    const int wm = wid & 1;          // 2 warp rows (64 rows each)
    const int wn = wid >> 1;         // 4 warp cols (32 cols each)

    // ---- MODE 7 dual-GEMM selection ----
    const __half* AP = A;
    const __half* BP = B;
    const float*  biasP = bias;
    float*        CfP = Cf;
    int rowBlockY = blockIdx.y;
    if (MODE == 7) {
        const int blocks0 = (M + BM - 1) >> 7;
        if ((int)blockIdx.y >= blocks0) {
            AP = tah; BP = tch; biasP = bias2; CfP = Cf2;
            M = M2; rowBlockY = blockIdx.y - blocks0;
        }
    }
    const int rowBlock = rowBlockY * BM;
    const int colBlock = blockIdx.x * BN;

    // ---- loader mapping: 2 threads per row, 16 halves each ----
    const int lrow = tid >> 1;               // 0..127
    const int lhs  = (tid & 1) * 16;         // halves
    const int gr  = rowBlock + lrow;
    const int grc = gr < M ? gr : (M - 1);
    const __half* arowp = AP + (size_t)grc * K;
    const __half* browp;
    if (MODE == 6) {
        const int n = colBlock + lrow;
        browp = BP + (size_t)(n & 511) * ldb + ((n >= 512) ? 1024 : 0);
    } else {
        browp = BP + (size_t)(colBlock + lrow) * ldb;
    }
    // MODE 8 phase-B pointers
    const __half* arowpB = nullptr;
    const __half* browpB = nullptr;
    if (MODE == 8) {
        arowpB = tah + (size_t)grc * K;
        browpB = tch + (size_t)(colBlock + lrow) * ldb;
    }

    const uint32_t aDst = sbase + (uint32_t)(lrow * LDA + lhs) * 2;
    const uint32_t bDst = sbase + (uint32_t)A_BYTES + (uint32_t)(lrow * LDA + lhs) * 2;

    const int nst = K >> 5;
    const int total = (MODE == 8) ? 2 * nst : nst;

    auto load_stage = [&](int i, int buf) {
        const uint32_t so = (uint32_t)(buf * STG_BYTES);
        const bool ph2 = (MODE == 8) && (i >= nst);
        const int kb = (((MODE == 8) ? (i & (nst - 1)) : i) << 5) + lhs;
        {
            const __half* src = (ph2 ? arowpB : arowp) + kb;
            cp16(aDst + so,      src);
            cp16(aDst + so + 16, src + 8);
        }
        {
            const __half* src = (ph2 ? browpB : browp) + kb;
            cp16(bDst + so,      src);
            cp16(bDst + so + 16, src + 8);
        }
        cp_commit();
    };

    // ---- fragment lane addressing (byte offsets within a stage) ----
    const uint32_t aFrag = sbase
        + (uint32_t)(((wm * 64 + (lane & 15)) * LDA + ((lane >> 4) << 3)) * 2);
    const uint32_t bFrag = sbase + (uint32_t)A_BYTES
        + (uint32_t)(((wn * 32 + ((lane & 7) | ((lane >> 4) << 3))) * LDA
                      + (((lane >> 3) & 1) << 3)) * 2);

    float acc[4][4][4];
#pragma unroll
    for (int i = 0; i < 4; i++)
#pragma unroll
        for (int j = 0; j < 4; j++)
#pragma unroll
            for (int q = 0; q < 4; q++) acc[i][j][q] = 0.f;

    load_stage(0, 0);
    load_stage(1, 1);
    load_stage(2, 2);

    int buf = 0;
    for (int i = 0; i < total; i++) {
        if (i >= total - 2) asm volatile("cp.async.wait_group 0;" ::: "memory");
        else                asm volatile("cp.async.wait_group 2;" ::: "memory");
        __syncthreads();

        if (i + 3 < total) {
            int nb = buf + 3; if (nb >= NSTG) nb -= NSTG;
            load_stage(i + 3, nb);
        }

        const uint32_t so = (uint32_t)(buf * STG_BYTES);
        // A-fragment streaming: B fragments resident (8 regs), A fetched per-mt
#pragma unroll
        for (int kk = 0; kk < 2; kk++) {
            uint32_t b[2][4];
            ldsm4(b[0], bFrag + so + (uint32_t)((kk * 16) * 2));
            ldsm4(b[1], bFrag + so + (uint32_t)((16 * LDA + kk * 16) * 2));
#pragma unroll
            for (int mt = 0; mt < 4; mt++) {
                uint32_t a[4];
                ldsm4(a, aFrag + so + (uint32_t)((mt * 16 * LDA + kk * 16) * 2));
#pragma unroll
                for (int nt = 0; nt < 4; nt++)
                    mma16816(acc[mt][nt], a, &b[nt >> 1][(nt & 1) * 2]);
            }
        }

        // MODE 8 mid-loop transform: after phase A completes, acc = relu(acc + c2[col])
        if (MODE == 8 && i == nst - 1) {
#pragma unroll
            for (int nt = 0; nt < 4; nt++) {
                const int c = colBlock + wn * 32 + nt * 8 + 2 * (lane & 3);
                const float bx = bias[c], by = bias[c + 1];
#pragma unroll
                for (int mt = 0; mt < 4; mt++) {
                    acc[mt][nt][0] = fmaxf(acc[mt][nt][0] + bx, 0.f);
                    acc[mt][nt][1] = fmaxf(acc[mt][nt][1] + by, 0.f);
                    acc[mt][nt][2] = fmaxf(acc[mt][nt][2] + bx, 0.f);
                    acc[mt][nt][3] = fmaxf(acc[mt][nt][3] + by, 0.f);
                }
            }
        }

        buf++; if (buf >= NSTG) buf -= NSTG;
    }

    // ---- epilogue ----
    const int region = colBlock >> 9;
#pragma unroll
    for (int mt = 0; mt < 4; mt++) {
        const int r0 = rowBlock + wm * 64 + mt * 16 + (lane >> 2);
        const int r1 = r0 + 8;
        const bool ok0 = r0 < M, ok1 = r1 < M;
        int s0 = 0, o0 = 0, s1 = 0, o1 = 0;
        if (MODE == 2) {
            if (region == 0) {
                if (ok0) s0 = edges[2 * r0];
                if (ok1) s1 = edges[2 * r1];
            } else if (region == 2) {
                if (ok0) o0 = edges[2 * r0 + 1];
                if (ok1) o1 = edges[2 * r1 + 1];
            }
        } else if (MODE == 4) {
            if (ok0) { s0 = edges[2 * r0]; o0 = edges[2 * r0 + 1]; }
            if (ok1) { s1 = edges[2 * r1]; o1 = edges[2 * r1 + 1]; }
        }
#pragma unroll
        for (int nt = 0; nt < 4; nt++) {
            const int c = colBlock + wn * 32 + nt * 8 + 2 * (lane & 3);
            float bx = 0.f, by = 0.f;
            if (MODE == 8) { bx = bias2[c]; by = bias2[c + 1]; }
            else if (MODE != 6) { bx = biasP[c]; by = biasP[c + 1]; }
            float v00 = acc[mt][nt][0] + bx, v01 = acc[mt][nt][1] + by;
            float v10 = acc[mt][nt][2] + bx, v11 = acc[mt][nt][3] + by;
            if (MODE == 0 || MODE == 2) {
                v00 = fmaxf(v00, 0.f); v01 = fmaxf(v01, 0.f);
                v10 = fmaxf(v10, 0.f); v11 = fmaxf(v11, 0.f);
            }
            if (MODE == 0 || MODE == 6) {
                if (ok0) *reinterpret_cast<__half2*>(Ch + (size_t)r0 * N + c) = __floats2half2_rn(v00, v01);
                if (ok1) *reinterpret_cast<__half2*>(Ch + (size_t)r1 * N + c) = __floats2half2_rn(v10, v11);
            } else if (MODE == 4) {
                if (ok0) {
                    __half2 ta = *reinterpret_cast<const __half2*>(tah + (size_t)s0 * 1024 + c);
                    __half2 tc = *reinterpret_cast<const __half2*>(tch + (size_t)o0 * 1024 + c);
                    float w0 = fmaxf(v00 + __low2float(ta) + __low2float(tc), 0.f);
                    float w1 = fmaxf(v01 + __high2float(ta) + __high2float(tc), 0.f);
                    *reinterpret_cast<__half2*>(Ch + (size_t)r0 * N + c) = __floats2half2_rn(w0, w1);
                }
                if (ok1) {
                    __half2 ta = *reinterpret_cast<const __half2*>(tah + (size_t)s1 * 1024 + c);
                    __half2 tc = *reinterpret_cast<const __half2*>(tch + (size_t)o1 * 1024 + c);
                    float w0 = fmaxf(v10 + __low2float(ta) + __low2float(tc), 0.f);
                    float w1 = fmaxf(v11 + __high2float(ta) + __high2float(tc), 0.f);
                    *reinterpret_cast<__half2*>(Ch + (size_t)r1 * N + c) = __floats2half2_rn(w0, w1);
                }
            } else if (MODE == 8) {
                if (ok0) *reinterpret_cast<float2*>(Cf + (size_t)r0 * N + c) = make_float2(v00, v01);
                if (ok1) *reinterpret_cast<float2*>(Cf + (size_t)r1 * N + c) = make_float2(v10, v11);
            } else if (MODE == 7) {
                if (ok0) {
                    float2 o = *reinterpret_cast<const float2*>(CfP + (size_t)r0 * N + c);
                    *reinterpret_cast<float2*>(CfP + (size_t)r0 * N + c) = make_float2(o.x + v00, o.y + v01);
                }
                if (ok1) {
                    float2 o = *reinterpret_cast<const float2*>(CfP + (size_t)r1 * N + c);
                    *reinterpret_cast<float2*>(CfP + (size_t)r1 * N + c) = make_float2(o.x + v10, o.y + v11);
                }
            } else { // MODE 2
                const int cl = c & 511;
                if (region == 1) {
                    if (ok0) *reinterpret_cast<float2*>(outp + (size_t)r0 * DIM + cl) = make_float2(v00, v01);
                    if (ok1) *reinterpret_cast<float2*>(outp + (size_t)r1 * DIM + cl) = make_float2(v10, v11);
                } else if (region == 0) {
                    if (ok0) red2(&pooled[(size_t)s0 * DIM + cl], v00, v01);
                    if (ok1) red2(&pooled[(size_t)s1 * DIM + cl], v10, v11);
                } else {
                    if (ok0) red2(&pooled[(size_t)o0 * DIM + cl], v00, v01);
                    if (ok1) red2(&pooled[(size_t)o1 * DIM + cl], v10, v11);
                }
            }
        }
    }
}

// ---------------- merged prep kernels ----------------
constexpr size_t PA0 = 2560000;            // obj f4 count
constexpr size_t PA1 = PA0 + 12800000;     // + pred f4
__global__ void prep_a_kernel(const float4* __restrict__ objv, const float4* __restrict__ predv,
                              uint2* __restrict__ objh, uint2* __restrict__ predh)
{
    size_t i = (size_t)blockIdx.x * blockDim.x + threadIdx.x;
    if (i < PA0)      objh[i] = cvt4(objv[i]);
    else if (i < PA1) predh[i - PA0] = cvt4(predv[i - PA0]);
}

constexpr size_t PB0 = 196608;             // W1 f4
constexpr size_t PB1 = PB0 + 196608;       // W2
constexpr size_t PB2 = PB1 + 65536;        // V1
constexpr size_t PB3 = PB2 + 65536;        // V2
constexpr size_t PB4 = PB3 + 65536;        // Po
constexpr size_t PB5 = PB4 + 65536;        // Pp
constexpr size_t PB6 = PB5 + 2560000;      // zero pooled (f4)
constexpr size_t PB7 = PB6 + 5000;         // zero counts (f4)
__global__ void prep_b_kernel(const float4* __restrict__ W1, const float4* __restrict__ W2,
                              const float4* __restrict__ V1, const float4* __restrict__ V2,
                              const float4* __restrict__ Po, const float4* __restrict__ Pp,
                              uint2* __restrict__ w1h, uint2* __restrict__ w2h,
                              uint2* __restrict__ v1h, uint2* __restrict__ v2h,
                              uint2* __restrict__ poh, uint2* __restrict__ pph,
                              float4* __restrict__ pooled, float4* __restrict__ counts)
{
    size_t i = (size_t)blockIdx.x * blockDim.x + threadIdx.x;
    if (i < PB0)      w1h[i] = cvt4(W1[i]);
    else if (i < PB1) w2h[i - PB0] = cvt4(W2[i - PB0]);
    else if (i < PB2) v1h[i - PB1] = cvt4(V1[i - PB1]);
    else if (i < PB3) v2h[i - PB2] = cvt4(V2[i - PB2]);
    else if (i < PB4) poh[i - PB3] = cvt4(Po[i - PB3]);
    else if (i < PB5) pph[i - PB4] = cvt4(Pp[i - PB4]);
    else if (i < PB6) pooled[i - PB5] = make_float4(0.f, 0.f, 0.f, 0.f);
    else if (i < PB7) counts[i - PB6] = make_float4(0.f, 0.f, 0.f, 0.f);
}

__global__ void count_kernel(const int* __restrict__ edges, float* counts) {
    int i = blockIdx.x * blockDim.x + threadIdx.x;
    if (i < NTRI) {
        atomicAdd(&counts[edges[2 * i]], 1.f);
        atomicAdd(&counts[edges[2 * i + 1]], 1.f);
    }
}

__global__ void normalize_kernel(const float* __restrict__ pooled,
                                 const float* __restrict__ counts,
                                 __half* __restrict__ poolh) {
    int i = blockIdx.x * blockDim.x + threadIdx.x;
    if (i < NOBJ * DIM) {
        float c = counts[i >> 9];
        poolh[i] = __float2half_rn(pooled[i] * (1.f / fmaxf(c, 1.f)));
    }
}

// ---------------- launcher ----------------
extern "C" void kernel_launch(void* const* d_in, const int* in_sizes, int n_in,
                              void* d_out, int out_size)
{
    const float* objv    = (const float*)d_in[0];
    const float* predv   = (const float*)d_in[1];
    const int*   edges   = (const int*)  d_in[2];
    const float* W1      = (const float*)d_in[3];
    const float* b1      = (const float*)d_in[4];
    const float* W2      = (const float*)d_in[5];
    const float* b2      = (const float*)d_in[6];
    const float* V1      = (const float*)d_in[7];
    const float* c1      = (const float*)d_in[8];
    const float* V2      = (const float*)d_in[9];
    const float* c2      = (const float*)d_in[10];
    const float* P_obj   = (const float*)d_in[11];
    const float* pb_obj  = (const float*)d_in[12];
    const float* P_pred  = (const float*)d_in[13];
    const float* pb_pred = (const float*)d_in[14];

    __half *hh, *poolh, *gh, *objh, *predh, *tach, *w1h, *w2h, *v1h, *v2h, *poh, *pph;
    float *pooledp, *countsp;
    cudaGetSymbolAddress((void**)&hh,      g_hh);
    cudaGetSymbolAddress((void**)&pooledp, g_pooled);
    cudaGetSymbolAddress((void**)&poolh,   g_poolh);
    cudaGetSymbolAddress((void**)&gh,      g_gh);
    cudaGetSymbolAddress((void**)&countsp, g_counts);
    cudaGetSymbolAddress((void**)&objh,    g_objh);
    cudaGetSymbolAddress((void**)&predh,   g_predh);
    cudaGetSymbolAddress((void**)&tach,    g_tach);
    cudaGetSymbolAddress((void**)&w1h,     g_W1h);
    cudaGetSymbolAddress((void**)&w2h,     g_W2h);
    cudaGetSymbolAddress((void**)&v1h,     g_V1h);
    cudaGetSymbolAddress((void**)&v2h,     g_V2h);
    cudaGetSymbolAddress((void**)&poh,     g_Poh);
    cudaGetSymbolAddress((void**)&pph,     g_Pph);

    cudaFuncSetAttribute(gemm_h<0>, cudaFuncAttributeMaxDynamicSharedMemorySize, SMEM_BYTES);
    cudaFuncSetAttribute(gemm_h<2>, cudaFuncAttributeMaxDynamicSharedMemorySize, SMEM_BYTES);
    cudaFuncSetAttribute(gemm_h<4>, cudaFuncAttributeMaxDynamicSharedMemorySize, SMEM_BYTES);
    cudaFuncSetAttribute(gemm_h<6>, cudaFuncAttributeMaxDynamicSharedMemorySize, SMEM_BYTES);
    cudaFuncSetAttribute(gemm_h<7>, cudaFuncAttributeMaxDynamicSharedMemorySize, SMEM_BYTES);
    cudaFuncSetAttribute(gemm_h<8>, cudaFuncAttributeMaxDynamicSharedMemorySize, SMEM_BYTES);

    float* out_obj = (float*)d_out;
    float* out_p   = (float*)d_out + (size_t)NOBJ * DIM;

    const int gMtri = (NTRI + BM - 1) / BM;   // 782
    const int gMobj = (NOBJ + BM - 1) / BM;   // 157

    // 0: convert inputs
    prep_a_kernel<<<(unsigned)((PA1 + 255) / 256), 256>>>(
        (const float4*)objv, (const float4*)predv, (uint2*)objh, (uint2*)predh);

    // 1: convert weights + zero pooled/counts
    prep_b_kernel<<<(unsigned)((PB7 + 255) / 256), 256>>>(
        (const float4*)W1, (const float4*)W2, (const float4*)V1, (const float4*)V2,
        (const float4*)P_obj, (const float4*)P_pred,
        (uint2*)w1h, (uint2*)w2h, (uint2*)v1h, (uint2*)v2h, (uint2*)poh, (uint2*)pph,
        (float4*)pooledp, (float4*)countsp);

    // 2: counts (after counts zeroed by prep_b)
    count_kernel<<<(NTRI + 255) / 256, 256>>>(edges, countsp);

    // 3: [T_a | T_c] = obj @ [W1a | W1c]^T  (merged, N=1024, split-B addressing)
    gemm_h<6><<<dim3(8, gMobj), NTHR, SMEM_BYTES>>>(
        objh, w1h, 1536, nullptr, tach, nullptr, NOBJ, 1024, 512,
        nullptr, nullptr, nullptr, nullptr, nullptr, nullptr, nullptr, 0);

    // 4: h = relu(pred @ W1b^T + T_a[s] + T_c[o] + b1)
    gemm_h<4><<<dim3(4, gMtri), NTHR, SMEM_BYTES>>>(
        predh, w1h + 512, 1536, b1, hh, nullptr, NTRI, 512, 512,
        edges, tach, tach + 512, nullptr, nullptr, nullptr, nullptr, 0);

    // 5: G2: new_t = relu(h @ W2^T + b2); split -> pooled reds + out_p
    gemm_h<2><<<dim3(12, gMtri), NTHR, SMEM_BYTES>>>(
        hh, w2h, 512, b2, nullptr, nullptr, NTRI, 1536, 512,
        edges, nullptr, nullptr, pooledp, out_p, nullptr, nullptr, 0);

    // 6: pooled /= max(counts,1) -> half
    normalize_kernel<<<(NOBJ * DIM + 255) / 256, 256>>>(pooledp, countsp, poolh);

    // 7: G3: g = relu(pooled @ V1^T + c1) -> half
    gemm_h<0><<<dim3(4, gMobj), NTHR, SMEM_BYTES>>>(
        poolh, v1h, 512, c1, gh, nullptr, NOBJ, 512, 512,
        nullptr, nullptr, nullptr, nullptr, nullptr, nullptr, nullptr, 0);

    // 8: G4+G5 fused (MODE 8):
    //    out_obj = relu(g @ V2^T + c2) + obj @ P_obj^T + pb_obj  (single pass, 1 store)
    gemm_h<8><<<dim3(4, gMobj), NTHR, SMEM_BYTES>>>(
        gh, v2h, 512, c2, nullptr, out_obj, NOBJ, 512, 512,
        nullptr, objh, poh, nullptr, nullptr, pb_obj, nullptr, 0);

    // 9: G6 (MODE 7, single part): out_p += pred @ P_pred^T + pb_pred
    gemm_h<7><<<dim3(4, gMtri), NTHR, SMEM_BYTES>>>(
        predh, pph, 512, pb_pred, nullptr, out_p, NTRI, 512, 512,
        nullptr, nullptr, nullptr, nullptr, nullptr, nullptr, nullptr, 0);
}

// round 16
// speedup vs baseline: 1.0993x; 1.0086x over previous
#include <cuda_runtime.h>
#include <cuda_fp16.h>
#include <cstdint>

#define NOBJ 20000
#define NTRI 100000
#define DIM  512

// ---------------- static device scratch (allocation-free) ----------------
__device__ __half g_hh[(size_t)NTRI * DIM];
__device__ float  g_pooled[(size_t)NOBJ * DIM];
__device__ __half g_poolh[(size_t)NOBJ * DIM];
__device__ __half g_gh[(size_t)NOBJ * DIM];
__device__ float  g_counts[NOBJ];
__device__ __half g_objh[(size_t)NOBJ * DIM];
__device__ __half g_predh[(size_t)NTRI * DIM];
__device__ __half g_tach[(size_t)NOBJ * 1024];  // [T_a | T_c] merged
__device__ __half g_W1h[512 * 1536];
__device__ __half g_W2h[1536 * 512];
__device__ __half g_V1h[512 * 512];
__device__ __half g_V2h[512 * 512];
__device__ __half g_Poh[512 * 512];
__device__ __half g_Pph[512 * 512];

// ---------------- helpers ----------------
__device__ __forceinline__ uint32_t smem_u32(const void* p) {
    uint32_t a;
    asm("{ .reg .u64 t; cvta.to.shared.u64 t, %1; cvt.u32.u64 %0, t; }" : "=r"(a) : "l"(p));
    return a;
}
__device__ __forceinline__ void cp16(uint32_t sdst, const void* gsrc) {
    asm volatile("cp.async.cg.shared.global [%0], [%1], 16;" :: "r"(sdst), "l"(gsrc) : "memory");
}
__device__ __forceinline__ void cp_commit() {
    asm volatile("cp.async.commit_group;" ::: "memory");
}
__device__ __forceinline__ void ldsm4(uint32_t* r, uint32_t addr) {
    asm volatile("ldmatrix.sync.aligned.m8n8.x4.shared.b16 {%0,%1,%2,%3}, [%4];"
                 : "=r"(r[0]), "=r"(r[1]), "=r"(r[2]), "=r"(r[3]) : "r"(addr));
}
// non-volatile: lets ptxas interleave MMAs with LDSMs
__device__ __forceinline__ void mma16816(float* d, const uint32_t* a, const uint32_t* b) {
    asm("mma.sync.aligned.m16n8k16.row.col.f32.f16.f16.f32 "
        "{%0,%1,%2,%3}, {%4,%5,%6,%7}, {%8,%9}, {%0,%1,%2,%3};"
        : "+f"(d[0]), "+f"(d[1]), "+f"(d[2]), "+f"(d[3])
        : "r"(a[0]), "r"(a[1]), "r"(a[2]), "r"(a[3]), "r"(b[0]), "r"(b[1]));
}
__device__ __forceinline__ void red2(float* p, float x, float y) {
    asm volatile("red.global.add.v2.f32 [%0], {%1,%2};"
                 :: "l"(p), "f"(x), "f"(y) : "memory");
}
__device__ __forceinline__ uint2 cvt4(float4 v) {
    __half2 h0 = __floats2half2_rn(v.x, v.y);
    __half2 h1 = __floats2half2_rn(v.z, v.w);
    uint2 u;
    u.x = *reinterpret_cast<uint32_t*>(&h0);
    u.y = *reinterpret_cast<uint32_t*>(&h1);
    return u;
}

// ---------------- GEMM config (round-11/14 best: 128x128, BK=32, 4 stages, 2 CTAs/SM) ----------------
constexpr int BM = 128, BN = 128, BK = 32;   // BK in halves
constexpr int LDA = 40;                      // smem row stride (halves); 80B rows
constexpr int NSTG = 4;
constexpr int A_BYTES = BM * LDA * 2;        // 10240
constexpr int B_BYTES = BN * LDA * 2;        // 10240
constexpr int STG_BYTES = A_BYTES + B_BYTES; // 20480
constexpr int SMEM_BYTES = NSTG * STG_BYTES; // 81920 -> 2 CTAs/SM
constexpr int NTHR = 256;                    // 8 warps, 2x4, 64x32 warp tile

// ---------------- fp16 MMA GEMM: epi(A[M,K] @ B[N,K_ldb]^T + bias) ----------------
// MODE 2: region = colBlock>>9: 0 -> red2 pooled[s]; 1 -> outp; 2 -> red2 pooled[o]  (relu)
// MODE 4: Ch = relu(v + bias + tah[edges[2r]*1024+c] + tch[edges[2r+1]*1024+c]) half
// MODE 6: Ch = v half (no bias/relu); split-B: col n<512 -> B+n*ldb, n>=512 -> B+(n-512)*ldb+1024
// MODE 8: fused dual-K GEMM: phase A (A,B) K=512, then acc=relu(acc+bias[col]),
//         then phase B (tah as A2, tch as B2) K=512; store Cf = acc + bias2[col]
// MODE 9: two GEMMs row-partitioned:
//         blockIdx.y < ceil(M/128): Ch = relu(v + bias) half            (G3)
//         else:                     Cf2 += v + bias2  (A2=tah, B2=tch)  (G6)
template <int MODE>
__global__ void __launch_bounds__(NTHR, 2)
gemm_h(const __half* __restrict__ A, const __half* __restrict__ B, int ldb,
       const float* __restrict__ bias,
       __half* __restrict__ Ch, float* __restrict__ Cf,
       int M, int N, int K,
       const int* __restrict__ edges,
       const __half* __restrict__ tah, const __half* __restrict__ tch,
       float* __restrict__ pooled, float* __restrict__ outp,
       const float* __restrict__ bias2, float* __restrict__ Cf2, int M2)
{
    extern __shared__ __align__(16) char dynsmem[];
    const uint32_t sbase = smem_u32(dynsmem);

    const int tid = threadIdx.x;
    const int wid = tid >> 5, lane = tid & 31;
    const int wm = wid & 1;          // 2 warp rows (64 rows each)
    const int wn = wid >> 1;         // 4 warp cols (32 cols each)

    // ---- MODE 9 dual-GEMM row-partition selection ----
    const __half* AP = A;
    const __half* BP = B;
    const float*  biasP = bias;
    float*        CfP = Cf;
    bool part2 = false;
    int rowBlockY = blockIdx.y;
    if (MODE == 9) {
        const int blocks0 = (M + BM - 1) >> 7;
        if ((int)blockIdx.y >= blocks0) {
            part2 = true;
            AP = tah; BP = tch; biasP = bias2; CfP = Cf2;
            M = M2; rowBlockY = blockIdx.y - blocks0;
        }
    }
    const int rowBlock = rowBlockY * BM;
    const int colBlock = blockIdx.x * BN;

    // ---- loader mapping: 2 threads per row, 16 halves each ----
    const int lrow = tid >> 1;               // 0..127
    const int lhs  = (tid & 1) * 16;         // halves
    const int gr  = rowBlock + lrow;
    const int grc = gr < M ? gr : (M - 1);
    const __half* arowp = AP + (size_t)grc * K;
    const __half* browp;
    if (MODE == 6) {
        const int n = colBlock + lrow;
        browp = BP + (size_t)(n & 511) * ldb + ((n >= 512) ? 1024 : 0);
    } else {
        browp = BP + (size_t)(colBlock + lrow) * ldb;
    }
    // MODE 8 phase-B pointers
    const __half* arowpB = nullptr;
    const __half* browpB = nullptr;
    if (MODE == 8) {
        arowpB = tah + (size_t)grc * K;
        browpB = tch + (size_t)(colBlock + lrow) * ldb;
    }

    const uint32_t aDst = sbase + (uint32_t)(lrow * LDA + lhs) * 2;
    const uint32_t bDst = sbase + (uint32_t)A_BYTES + (uint32_t)(lrow * LDA + lhs) * 2;

    const int nst = K >> 5;
    const int total = (MODE == 8) ? 2 * nst : nst;

    auto load_stage = [&](int i, int buf) {
        const uint32_t so = (uint32_t)(buf * STG_BYTES);
        const bool ph2 = (MODE == 8) && (i >= nst);
        const int kb = (((MODE == 8) ? (i & (nst - 1)) : i) << 5) + lhs;
        {
            const __half* src = (ph2 ? arowpB : arowp) + kb;
            cp16(aDst + so,      src);
            cp16(aDst + so + 16, src + 8);
        }
        {
            const __half* src = (ph2 ? browpB : browp) + kb;
            cp16(bDst + so,      src);
            cp16(bDst + so + 16, src + 8);
        }
        cp_commit();
    };

    // ---- fragment lane addressing (byte offsets within a stage) ----
    const uint32_t aFrag = sbase
        + (uint32_t)(((wm * 64 + (lane & 15)) * LDA + ((lane >> 4) << 3)) * 2);
    const uint32_t bFrag = sbase + (uint32_t)A_BYTES
        + (uint32_t)(((wn * 32 + ((lane & 7) | ((lane >> 4) << 3))) * LDA
                      + (((lane >> 3) & 1) << 3)) * 2);

    float acc[4][4][4];
#pragma unroll
    for (int i = 0; i < 4; i++)
#pragma unroll
        for (int j = 0; j < 4; j++)
#pragma unroll
            for (int q = 0; q < 4; q++) acc[i][j][q] = 0.f;

    load_stage(0, 0);
    load_stage(1, 1);
    load_stage(2, 2);

    int buf = 0;
    for (int i = 0; i < total; i++) {
        if (i >= total - 2) asm volatile("cp.async.wait_group 0;" ::: "memory");
        else                asm volatile("cp.async.wait_group 2;" ::: "memory");
        __syncthreads();

        if (i + 3 < total) {
            int nb = buf + 3; if (nb >= NSTG) nb -= NSTG;
            load_stage(i + 3, nb);
        }

        const uint32_t so = (uint32_t)(buf * STG_BYTES);
        // A-fragment streaming: B fragments resident (8 regs), A fetched per-mt
#pragma unroll
        for (int kk = 0; kk < 2; kk++) {
            uint32_t b[2][4];
            ldsm4(b[0], bFrag + so + (uint32_t)((kk * 16) * 2));
            ldsm4(b[1], bFrag + so + (uint32_t)((16 * LDA + kk * 16) * 2));
#pragma unroll
            for (int mt = 0; mt < 4; mt++) {
                uint32_t a[4];
                ldsm4(a, aFrag + so + (uint32_t)((mt * 16 * LDA + kk * 16) * 2));
#pragma unroll
                for (int nt = 0; nt < 4; nt++)
                    mma16816(acc[mt][nt], a, &b[nt >> 1][(nt & 1) * 2]);
            }
        }

        // MODE 8 mid-loop transform: after phase A completes, acc = relu(acc + c2[col])
        if (MODE == 8 && i == nst - 1) {
#pragma unroll
            for (int nt = 0; nt < 4; nt++) {
                const int c = colBlock + wn * 32 + nt * 8 + 2 * (lane & 3);
                const float bx = bias[c], by = bias[c + 1];
#pragma unroll
                for (int mt = 0; mt < 4; mt++) {
                    acc[mt][nt][0] = fmaxf(acc[mt][nt][0] + bx, 0.f);
                    acc[mt][nt][1] = fmaxf(acc[mt][nt][1] + by, 0.f);
                    acc[mt][nt][2] = fmaxf(acc[mt][nt][2] + bx, 0.f);
                    acc[mt][nt][3] = fmaxf(acc[mt][nt][3] + by, 0.f);
                }
            }
        }

        buf++; if (buf >= NSTG) buf -= NSTG;
    }

    // ---- epilogue ----
    const int region = colBlock >> 9;
#pragma unroll
    for (int mt = 0; mt < 4; mt++) {
        const int r0 = rowBlock + wm * 64 + mt * 16 + (lane >> 2);
        const int r1 = r0 + 8;
        const bool ok0 = r0 < M, ok1 = r1 < M;
        int s0 = 0, o0 = 0, s1 = 0, o1 = 0;
        if (MODE == 2) {
            if (region == 0) {
                if (ok0) s0 = edges[2 * r0];
                if (ok1) s1 = edges[2 * r1];
            } else if (region == 2) {
                if (ok0) o0 = edges[2 * r0 + 1];
                if (ok1) o1 = edges[2 * r1 + 1];
            }
        } else if (MODE == 4) {
            if (ok0) { s0 = edges[2 * r0]; o0 = edges[2 * r0 + 1]; }
            if (ok1) { s1 = edges[2 * r1]; o1 = edges[2 * r1 + 1]; }
        }
#pragma unroll
        for (int nt = 0; nt < 4; nt++) {
            const int c = colBlock + wn * 32 + nt * 8 + 2 * (lane & 3);
            float bx = 0.f, by = 0.f;
            if (MODE == 8) { bx = bias2[c]; by = bias2[c + 1]; }
            else if (MODE != 6) { bx = biasP[c]; by = biasP[c + 1]; }
            float v00 = acc[mt][nt][0] + bx, v01 = acc[mt][nt][1] + by;
            float v10 = acc[mt][nt][2] + bx, v11 = acc[mt][nt][3] + by;
            if (MODE == 2) {
                v00 = fmaxf(v00, 0.f); v01 = fmaxf(v01, 0.f);
                v10 = fmaxf(v10, 0.f); v11 = fmaxf(v11, 0.f);
            }
            if (MODE == 6) {
                if (ok0) *reinterpret_cast<__half2*>(Ch + (size_t)r0 * N + c) = __floats2half2_rn(v00, v01);
                if (ok1) *reinterpret_cast<__half2*>(Ch + (size_t)r1 * N + c) = __floats2half2_rn(v10, v11);
            } else if (MODE == 4) {
                if (ok0) {
                    __half2 ta = *reinterpret_cast<const __half2*>(tah + (size_t)s0 * 1024 + c);
                    __half2 tc = *reinterpret_cast<const __half2*>(tch + (size_t)o0 * 1024 + c);
                    float w0 = fmaxf(v00 + __low2float(ta) + __low2float(tc), 0.f);
                    float w1 = fmaxf(v01 + __high2float(ta) + __high2float(tc), 0.f);
                    *reinterpret_cast<__half2*>(Ch + (size_t)r0 * N + c) = __floats2half2_rn(w0, w1);
                }
                if (ok1) {
                    __half2 ta = *reinterpret_cast<const __half2*>(tah + (size_t)s1 * 1024 + c);
                    __half2 tc = *reinterpret_cast<const __half2*>(tch + (size_t)o1 * 1024 + c);
                    float w0 = fmaxf(v10 + __low2float(ta) + __low2float(tc), 0.f);
                    float w1 = fmaxf(v11 + __high2float(ta) + __high2float(tc), 0.f);
                    *reinterpret_cast<__half2*>(Ch + (size_t)r1 * N + c) = __floats2half2_rn(w0, w1);
                }
            } else if (MODE == 8) {
                if (ok0) *reinterpret_cast<float2*>(Cf + (size_t)r0 * N + c) = make_float2(v00, v01);
                if (ok1) *reinterpret_cast<float2*>(Cf + (size_t)r1 * N + c) = make_float2(v10, v11);
            } else if (MODE == 9) {
                if (!part2) {
                    // G3: gh = relu(v + c1) half
                    v00 = fmaxf(v00, 0.f); v01 = fmaxf(v01, 0.f);
                    v10 = fmaxf(v10, 0.f); v11 = fmaxf(v11, 0.f);
                    if (ok0) *reinterpret_cast<__half2*>(Ch + (size_t)r0 * N + c) = __floats2half2_rn(v00, v01);
                    if (ok1) *reinterpret_cast<__half2*>(Ch + (size_t)r1 * N + c) = __floats2half2_rn(v10, v11);
                } else {
                    // G6: out_p += v + pb_pred
                    if (ok0) {
                        float2 o = *reinterpret_cast<const float2*>(CfP + (size_t)r0 * N + c);
                        *reinterpret_cast<float2*>(CfP + (size_t)r0 * N + c) = make_float2(o.x + v00, o.y + v01);
                    }
                    if (ok1) {
                        float2 o = *reinterpret_cast<const float2*>(CfP + (size_t)r1 * N + c);
                        *reinterpret_cast<float2*>(CfP + (size_t)r1 * N + c) = make_float2(o.x + v10, o.y + v11);
                    }
                }
            } else { // MODE 2
                const int cl = c & 511;
                if (region == 1) {
                    if (ok0) *reinterpret_cast<float2*>(outp + (size_t)r0 * DIM + cl) = make_float2(v00, v01);
                    if (ok1) *reinterpret_cast<float2*>(outp + (size_t)r1 * DIM + cl) = make_float2(v10, v11);
                } else if (region == 0) {
                    if (ok0) red2(&pooled[(size_t)s0 * DIM + cl], v00, v01);
                    if (ok1) red2(&pooled[(size_t)s1 * DIM + cl], v10, v11);
                } else {
                    if (ok0) red2(&pooled[(size_t)o0 * DIM + cl], v00, v01);
                    if (ok1) red2(&pooled[(size_t)o1 * DIM + cl], v10, v11);
                }
            }
        }
    }
}

// ---------------- merged prep kernels ----------------
constexpr size_t PA0 = 2560000;            // obj f4 count
constexpr size_t PA1 = PA0 + 12800000;     // + pred f4
__global__ void prep_a_kernel(const float4* __restrict__ objv, const float4* __restrict__ predv,
                              uint2* __restrict__ objh, uint2* __restrict__ predh)
{
    size_t i = (size_t)blockIdx.x * blockDim.x + threadIdx.x;
    if (i < PA0)      objh[i] = cvt4(objv[i]);
    else if (i < PA1) predh[i - PA0] = cvt4(predv[i - PA0]);
}

constexpr size_t PB0 = 196608;             // W1 f4
constexpr size_t PB1 = PB0 + 196608;       // W2
constexpr size_t PB2 = PB1 + 65536;        // V1
constexpr size_t PB3 = PB2 + 65536;        // V2
constexpr size_t PB4 = PB3 + 65536;        // Po
constexpr size_t PB5 = PB4 + 65536;        // Pp
constexpr size_t PB6 = PB5 + 2560000;      // zero pooled (f4)
constexpr size_t PB7 = PB6 + 5000;         // zero counts (f4)
__global__ void prep_b_kernel(const float4* __restrict__ W1, const float4* __restrict__ W2,
                              const float4* __restrict__ V1, const float4* __restrict__ V2,
                              const float4* __restrict__ Po, const float4* __restrict__ Pp,
                              uint2* __restrict__ w1h, uint2* __restrict__ w2h,
                              uint2* __restrict__ v1h, uint2* __restrict__ v2h,
                              uint2* __restrict__ poh, uint2* __restrict__ pph,
                              float4* __restrict__ pooled, float4* __restrict__ counts)
{
    size_t i = (size_t)blockIdx.x * blockDim.x + threadIdx.x;
    if (i < PB0)      w1h[i] = cvt4(W1[i]);
    else if (i < PB1) w2h[i - PB0] = cvt4(W2[i - PB0]);
    else if (i < PB2) v1h[i - PB1] = cvt4(V1[i - PB1]);
    else if (i < PB3) v2h[i - PB2] = cvt4(V2[i - PB2]);
    else if (i < PB4) poh[i - PB3] = cvt4(Po[i - PB3]);
    else if (i < PB5) pph[i - PB4] = cvt4(Pp[i - PB4]);
    else if (i < PB6) pooled[i - PB5] = make_float4(0.f, 0.f, 0.f, 0.f);
    else if (i < PB7) counts[i - PB6] = make_float4(0.f, 0.f, 0.f, 0.f);
}

__global__ void count_kernel(const int* __restrict__ edges, float* counts) {
    int i = blockIdx.x * blockDim.x + threadIdx.x;
    if (i < NTRI) {
        atomicAdd(&counts[edges[2 * i]], 1.f);
        atomicAdd(&counts[edges[2 * i + 1]], 1.f);
    }
}

__global__ void normalize_kernel(const float* __restrict__ pooled,
                                 const float* __restrict__ counts,
                                 __half* __restrict__ poolh) {
    int i = blockIdx.x * blockDim.x + threadIdx.x;
    if (i < NOBJ * DIM) {
        float c = counts[i >> 9];
        poolh[i] = __float2half_rn(pooled[i] * (1.f / fmaxf(c, 1.f)));
    }
}

// ---------------- launcher ----------------
extern "C" void kernel_launch(void* const* d_in, const int* in_sizes, int n_in,
                              void* d_out, int out_size)
{
    const float* objv    = (const float*)d_in[0];
    const float* predv   = (const float*)d_in[1];
    const int*   edges   = (const int*)  d_in[2];
    const float* W1      = (const float*)d_in[3];
    const float* b1      = (const float*)d_in[4];
    const float* W2      = (const float*)d_in[5];
    const float* b2      = (const float*)d_in[6];
    const float* V1      = (const float*)d_in[7];
    const float* c1      = (const float*)d_in[8];
    const float* V2      = (const float*)d_in[9];
    const float* c2      = (const float*)d_in[10];
    const float* P_obj   = (const float*)d_in[11];
    const float* pb_obj  = (const float*)d_in[12];
    const float* P_pred  = (const float*)d_in[13];
    const float* pb_pred = (const float*)d_in[14];

    __half *hh, *poolh, *gh, *objh, *predh, *tach, *w1h, *w2h, *v1h, *v2h, *poh, *pph;
    float *pooledp, *countsp;
    cudaGetSymbolAddress((void**)&hh,      g_hh);
    cudaGetSymbolAddress((void**)&pooledp, g_pooled);
    cudaGetSymbolAddress((void**)&poolh,   g_poolh);
    cudaGetSymbolAddress((void**)&gh,      g_gh);
    cudaGetSymbolAddress((void**)&countsp, g_counts);
    cudaGetSymbolAddress((void**)&objh,    g_objh);
    cudaGetSymbolAddress((void**)&predh,   g_predh);
    cudaGetSymbolAddress((void**)&tach,    g_tach);
    cudaGetSymbolAddress((void**)&w1h,     g_W1h);
    cudaGetSymbolAddress((void**)&w2h,     g_W2h);
    cudaGetSymbolAddress((void**)&v1h,     g_V1h);
    cudaGetSymbolAddress((void**)&v2h,     g_V2h);
    cudaGetSymbolAddress((void**)&poh,     g_Poh);
    cudaGetSymbolAddress((void**)&pph,     g_Pph);

    cudaFuncSetAttribute(gemm_h<2>, cudaFuncAttributeMaxDynamicSharedMemorySize, SMEM_BYTES);
    cudaFuncSetAttribute(gemm_h<4>, cudaFuncAttributeMaxDynamicSharedMemorySize, SMEM_BYTES);
    cudaFuncSetAttribute(gemm_h<6>, cudaFuncAttributeMaxDynamicSharedMemorySize, SMEM_BYTES);
    cudaFuncSetAttribute(gemm_h<8>, cudaFuncAttributeMaxDynamicSharedMemorySize, SMEM_BYTES);
    cudaFuncSetAttribute(gemm_h<9>, cudaFuncAttributeMaxDynamicSharedMemorySize, SMEM_BYTES);

    float* out_obj = (float*)d_out;
    float* out_p   = (float*)d_out + (size_t)NOBJ * DIM;

    const int gMtri = (NTRI + BM - 1) / BM;   // 782
    const int gMobj = (NOBJ + BM - 1) / BM;   // 157

    // 0: convert inputs
    prep_a_kernel<<<(unsigned)((PA1 + 255) / 256), 256>>>(
        (const float4*)objv, (const float4*)predv, (uint2*)objh, (uint2*)predh);

    // 1: convert weights + zero pooled/counts
    prep_b_kernel<<<(unsigned)((PB7 + 255) / 256), 256>>>(
        (const float4*)W1, (const float4*)W2, (const float4*)V1, (const float4*)V2,
        (const float4*)P_obj, (const float4*)P_pred,
        (uint2*)w1h, (uint2*)w2h, (uint2*)v1h, (uint2*)v2h, (uint2*)poh, (uint2*)pph,
        (float4*)pooledp, (float4*)countsp);

    // 2: counts (after counts zeroed by prep_b)
    count_kernel<<<(NTRI + 255) / 256, 256>>>(edges, countsp);

    // 3: [T_a | T_c] = obj @ [W1a | W1c]^T  (merged, N=1024, split-B addressing)
    gemm_h<6><<<dim3(8, gMobj), NTHR, SMEM_BYTES>>>(
        objh, w1h, 1536, nullptr, tach, nullptr, NOBJ, 1024, 512,
        nullptr, nullptr, nullptr, nullptr, nullptr, nullptr, nullptr, 0);

    // 4: h = relu(pred @ W1b^T + T_a[s] + T_c[o] + b1)
    gemm_h<4><<<dim3(4, gMtri), NTHR, SMEM_BYTES>>>(
        predh, w1h + 512, 1536, b1, hh, nullptr, NTRI, 512, 512,
        edges, tach, tach + 512, nullptr, nullptr, nullptr, nullptr, 0);

    // 5: G2: new_t = relu(h @ W2^T + b2); split -> pooled reds + out_p
    gemm_h<2><<<dim3(12, gMtri), NTHR, SMEM_BYTES>>>(
        hh, w2h, 512, b2, nullptr, nullptr, NTRI, 1536, 512,
        edges, nullptr, nullptr, pooledp, out_p, nullptr, nullptr, 0);

    // 6: pooled /= max(counts,1) -> half
    normalize_kernel<<<(NOBJ * DIM + 255) / 256, 256>>>(pooledp, countsp, poolh);

    // 7: G3 || G6 packed (MODE 9):
    //    rows [0,157):  gh = relu(pooled @ V1^T + c1)            (half)
    //    rows [157,..): out_p += pred @ P_pred^T + pb_pred       (float +=)
    gemm_h<9><<<dim3(4, gMobj + gMtri), NTHR, SMEM_BYTES>>>(
        poolh, v1h, 512, c1, gh, nullptr, NOBJ, 512, 512,
        nullptr, predh, pph, nullptr, nullptr, pb_pred, out_p, NTRI);

    // 8: G4+G5 fused (MODE 8):
    //    out_obj = relu(g @ V2^T + c2) + obj @ P_obj^T + pb_obj  (single pass, 1 store)
    gemm_h<8><<<dim3(4, gMobj), NTHR, SMEM_BYTES>>>(
        gh, v2h, 512, c2, nullptr, out_obj, NOBJ, 512, 512,
        nullptr, objh, poh, nullptr, nullptr, pb_obj, nullptr, 0);
}

// round 17
// speedup vs baseline: 1.1006x; 1.0012x over previous
#include <cuda_runtime.h>
#include <cuda_fp16.h>
#include <cstdint>

#define NOBJ 20000
#define NTRI 100000
#define DIM  512

// ---------------- static device scratch (allocation-free) ----------------
__device__ __half g_hh[(size_t)NTRI * DIM];
__device__ float  g_pooled[(size_t)NOBJ * DIM];
__device__ __half g_poolh[(size_t)NOBJ * DIM];
__device__ __half g_gh[(size_t)NOBJ * DIM];
__device__ float  g_counts[NOBJ];
__device__ __half g_objh[(size_t)NOBJ * DIM];
__device__ __half g_predh[(size_t)NTRI * DIM];
__device__ __half g_tach[(size_t)NOBJ * 1024];  // [T_a | T_c] merged
__device__ __half g_W1h[512 * 1536];
__device__ __half g_W2h[1536 * 512];
__device__ __half g_V1h[512 * 512];
__device__ __half g_V2h[512 * 512];
__device__ __half g_Poh[512 * 512];
__device__ __half g_Pph[512 * 512];

// ---------------- helpers ----------------
__device__ __forceinline__ uint32_t smem_u32(const void* p) {
    uint32_t a;
    asm("{ .reg .u64 t; cvta.to.shared.u64 t, %1; cvt.u32.u64 %0, t; }" : "=r"(a) : "l"(p));
    return a;
}
__device__ __forceinline__ void cp16(uint32_t sdst, const void* gsrc) {
    asm volatile("cp.async.cg.shared.global [%0], [%1], 16;" :: "r"(sdst), "l"(gsrc) : "memory");
}
__device__ __forceinline__ void cp_commit() {
    asm volatile("cp.async.commit_group;" ::: "memory");
}
__device__ __forceinline__ void ldsm4(uint32_t* r, uint32_t addr) {
    asm volatile("ldmatrix.sync.aligned.m8n8.x4.shared.b16 {%0,%1,%2,%3}, [%4];"
                 : "=r"(r[0]), "=r"(r[1]), "=r"(r[2]), "=r"(r[3]) : "r"(addr));
}
// non-volatile: lets ptxas interleave MMAs with LDSMs
__device__ __forceinline__ void mma16816(float* d, const uint32_t* a, const uint32_t* b) {
    asm("mma.sync.aligned.m16n8k16.row.col.f32.f16.f16.f32 "
        "{%0,%1,%2,%3}, {%4,%5,%6,%7}, {%8,%9}, {%0,%1,%2,%3};"
        : "+f"(d[0]), "+f"(d[1]), "+f"(d[2]), "+f"(d[3])
        : "r"(a[0]), "r"(a[1]), "r"(a[2]), "r"(a[3]), "r"(b[0]), "r"(b[1]));
}
__device__ __forceinline__ void red2(float* p, float x, float y) {
    asm volatile("red.global.add.v2.f32 [%0], {%1,%2};"
                 :: "l"(p), "f"(x), "f"(y) : "memory");
}
__device__ __forceinline__ uint2 cvt4(float4 v) {
    __half2 h0 = __floats2half2_rn(v.x, v.y);
    __half2 h1 = __floats2half2_rn(v.z, v.w);
    uint2 u;
    u.x = *reinterpret_cast<uint32_t*>(&h0);
    u.y = *reinterpret_cast<uint32_t*>(&h1);
    return u;
}

// ---------------- GEMM config (round-11/14 best: 128x128, BK=32, 4 stages, 2 CTAs/SM) ----------------
constexpr int BM = 128, BN = 128, BK = 32;   // BK in halves
constexpr int LDA = 40;                      // smem row stride (halves); 80B rows
constexpr int NSTG = 4;
constexpr int A_BYTES = BM * LDA * 2;        // 10240
constexpr int B_BYTES = BN * LDA * 2;        // 10240
constexpr int STG_BYTES = A_BYTES + B_BYTES; // 20480
constexpr int SMEM_BYTES = NSTG * STG_BYTES; // 81920 -> 2 CTAs/SM
constexpr int NTHR = 256;                    // 8 warps, 2x4, 64x32 warp tile

// ---------------- fp16 MMA GEMM: epi(A[M,K] @ B[N,K_ldb]^T + bias) ----------------
// MODE 2: region = colBlock>>9: 0 -> red2 pooled[s]; 1 -> outp; 2 -> red2 pooled[o]  (relu)
// MODE 4: Ch = relu(v + bias + tah[edges[2r]*1024+c] + tch[edges[2r+1]*1024+c]) half
// MODE 6: Ch = v half (no bias/relu); split-B: col n<512 -> B+n*ldb, n>=512 -> B+(n-512)*ldb+1024
// MODE 8: fused dual-K GEMM: phase A (A,B) K=512, then acc=relu(acc+bias[col]),
//         then phase B (tah as A2, tch as B2) K=512; store Cf = acc + bias2[col]
// MODE 9: two GEMMs row-partitioned:
//         blockIdx.y < ceil(M/128): Ch = relu(v + bias) half            (G3)
//         else:                     Cf2 += v + bias2  (A2=tah, B2=tch)  (G6)
template <int MODE>
__global__ void __launch_bounds__(NTHR, 2)
gemm_h(const __half* __restrict__ A, const __half* __restrict__ B, int ldb,
       const float* __restrict__ bias,
       __half* __restrict__ Ch, float* __restrict__ Cf,
       int M, int N, int K,
       const int* __restrict__ edges,
       const __half* __restrict__ tah, const __half* __restrict__ tch,
       float* __restrict__ pooled, float* __restrict__ outp,
       const float* __restrict__ bias2, float* __restrict__ Cf2, int M2)
{
    extern __shared__ __align__(16) char dynsmem[];
    const uint32_t sbase = smem_u32(dynsmem);

    const int tid = threadIdx.x;
    const int wid = tid >> 5, lane = tid & 31;
    const int wm = wid & 1;          // 2 warp rows (64 rows each)
    const int wn = wid >> 1;         // 4 warp cols (32 cols each)

    // ---- MODE 9 dual-GEMM row-partition selection ----
    const __half* AP = A;
    const __half* BP = B;
    const float*  biasP = bias;
    float*        CfP = Cf;
    bool part2 = false;
    int rowBlockY = blockIdx.y;
    if (MODE == 9) {
        const int blocks0 = (M + BM - 1) >> 7;
        if ((int)blockIdx.y >= blocks0) {
            part2 = true;
            AP = tah; BP = tch; biasP = bias2; CfP = Cf2;
            M = M2; rowBlockY = blockIdx.y - blocks0;
        }
    }
    const int rowBlock = rowBlockY * BM;
    const int colBlock = blockIdx.x * BN;

    // ---- loader mapping: 2 threads per row, 16 halves each ----
    const int lrow = tid >> 1;               // 0..127
    const int lhs  = (tid & 1) * 16;         // halves
    const int gr  = rowBlock + lrow;
    const int grc = gr < M ? gr : (M - 1);
    const __half* arowp = AP + (size_t)grc * K;
    const __half* browp;
    if (MODE == 6) {
        const int n = colBlock + lrow;
        browp = BP + (size_t)(n & 511) * ldb + ((n >= 512) ? 1024 : 0);
    } else {
        browp = BP + (size_t)(colBlock + lrow) * ldb;
    }
    // MODE 8 phase-B pointers
    const __half* arowpB = nullptr;
    const __half* browpB = nullptr;
    if (MODE == 8) {
        arowpB = tah + (size_t)grc * K;
        browpB = tch + (size_t)(colBlock + lrow) * ldb;
    }

    const uint32_t aDst = sbase + (uint32_t)(lrow * LDA + lhs) * 2;
    const uint32_t bDst = sbase + (uint32_t)A_BYTES + (uint32_t)(lrow * LDA + lhs) * 2;

    const int nst = K >> 5;
    const int total = (MODE == 8) ? 2 * nst : nst;

    auto load_stage = [&](int i, int buf) {
        const uint32_t so = (uint32_t)(buf * STG_BYTES);
        const bool ph2 = (MODE == 8) && (i >= nst);
        const int kb = (((MODE == 8) ? (i & (nst - 1)) : i) << 5) + lhs;
        {
            const __half* src = (ph2 ? arowpB : arowp) + kb;
            cp16(aDst + so,      src);
            cp16(aDst + so + 16, src + 8);
        }
        {
            const __half* src = (ph2 ? browpB : browp) + kb;
            cp16(bDst + so,      src);
            cp16(bDst + so + 16, src + 8);
        }
        cp_commit();
    };

    // ---- fragment lane addressing (byte offsets within a stage) ----
    const uint32_t aFrag = sbase
        + (uint32_t)(((wm * 64 + (lane & 15)) * LDA + ((lane >> 4) << 3)) * 2);
    const uint32_t bFrag = sbase + (uint32_t)A_BYTES
        + (uint32_t)(((wn * 32 + ((lane & 7) | ((lane >> 4) << 3))) * LDA
                      + (((lane >> 3) & 1) << 3)) * 2);

    float acc[4][4][4];
#pragma unroll
    for (int i = 0; i < 4; i++)
#pragma unroll
        for (int j = 0; j < 4; j++)
#pragma unroll
            for (int q = 0; q < 4; q++) acc[i][j][q] = 0.f;

    load_stage(0, 0);
    load_stage(1, 1);
    load_stage(2, 2);

    int buf = 0;
    for (int i = 0; i < total; i++) {
        if (i >= total - 2) asm volatile("cp.async.wait_group 0;" ::: "memory");
        else                asm volatile("cp.async.wait_group 2;" ::: "memory");
        __syncthreads();

        if (i + 3 < total) {
            int nb = buf + 3; if (nb >= NSTG) nb -= NSTG;
            load_stage(i + 3, nb);
        }

        const uint32_t so = (uint32_t)(buf * STG_BYTES);
        // A-fragment streaming: B fragments resident (8 regs), A fetched per-mt
#pragma unroll
        for (int kk = 0; kk < 2; kk++) {
            uint32_t b[2][4];
            ldsm4(b[0], bFrag + so + (uint32_t)((kk * 16) * 2));
            ldsm4(b[1], bFrag + so + (uint32_t)((16 * LDA + kk * 16) * 2));
#pragma unroll
            for (int mt = 0; mt < 4; mt++) {
                uint32_t a[4];
                ldsm4(a, aFrag + so + (uint32_t)((mt * 16 * LDA + kk * 16) * 2));
#pragma unroll
                for (int nt = 0; nt < 4; nt++)
                    mma16816(acc[mt][nt], a, &b[nt >> 1][(nt & 1) * 2]);
            }
        }

        // MODE 8 mid-loop transform: after phase A completes, acc = relu(acc + c2[col])
        if (MODE == 8 && i == nst - 1) {
#pragma unroll
            for (int nt = 0; nt < 4; nt++) {
                const int c = colBlock + wn * 32 + nt * 8 + 2 * (lane & 3);
                const float bx = bias[c], by = bias[c + 1];
#pragma unroll
                for (int mt = 0; mt < 4; mt++) {
                    acc[mt][nt][0] = fmaxf(acc[mt][nt][0] + bx, 0.f);
                    acc[mt][nt][1] = fmaxf(acc[mt][nt][1] + by, 0.f);
                    acc[mt][nt][2] = fmaxf(acc[mt][nt][2] + bx, 0.f);
                    acc[mt][nt][3] = fmaxf(acc[mt][nt][3] + by, 0.f);
                }
            }
        }

        buf++; if (buf >= NSTG) buf -= NSTG;
    }

    // ---- epilogue ----
    const int region = colBlock >> 9;
#pragma unroll
    for (int mt = 0; mt < 4; mt++) {
        const int r0 = rowBlock + wm * 64 + mt * 16 + (lane >> 2);
        const int r1 = r0 + 8;
        const bool ok0 = r0 < M, ok1 = r1 < M;
        int s0 = 0, o0 = 0, s1 = 0, o1 = 0;
        if (MODE == 2) {
            if (region == 0) {
                if (ok0) s0 = edges[2 * r0];
                if (ok1) s1 = edges[2 * r1];
            } else if (region == 2) {
                if (ok0) o0 = edges[2 * r0 + 1];
                if (ok1) o1 = edges[2 * r1 + 1];
            }
        } else if (MODE == 4) {
            if (ok0) { s0 = edges[2 * r0]; o0 = edges[2 * r0 + 1]; }
            if (ok1) { s1 = edges[2 * r1]; o1 = edges[2 * r1 + 1]; }
        }
#pragma unroll
        for (int nt = 0; nt < 4; nt++) {
            const int c = colBlock + wn * 32 + nt * 8 + 2 * (lane & 3);
            float bx = 0.f, by = 0.f;
            if (MODE == 8) { bx = bias2[c]; by = bias2[c + 1]; }
            else if (MODE != 6) { bx = biasP[c]; by = biasP[c + 1]; }
            float v00 = acc[mt][nt][0] + bx, v01 = acc[mt][nt][1] + by;
            float v10 = acc[mt][nt][2] + bx, v11 = acc[mt][nt][3] + by;
            if (MODE == 2) {
                v00 = fmaxf(v00, 0.f); v01 = fmaxf(v01, 0.f);
                v10 = fmaxf(v10, 0.f); v11 = fmaxf(v11, 0.f);
            }
            if (MODE == 6) {
                if (ok0) *reinterpret_cast<__half2*>(Ch + (size_t)r0 * N + c) = __floats2half2_rn(v00, v01);
                if (ok1) *reinterpret_cast<__half2*>(Ch + (size_t)r1 * N + c) = __floats2half2_rn(v10, v11);
            } else if (MODE == 4) {
                if (ok0) {
                    __half2 ta = *reinterpret_cast<const __half2*>(tah + (size_t)s0 * 1024 + c);
                    __half2 tc = *reinterpret_cast<const __half2*>(tch + (size_t)o0 * 1024 + c);
                    float w0 = fmaxf(v00 + __low2float(ta) + __low2float(tc), 0.f);
                    float w1 = fmaxf(v01 + __high2float(ta) + __high2float(tc), 0.f);
                    *reinterpret_cast<__half2*>(Ch + (size_t)r0 * N + c) = __floats2half2_rn(w0, w1);
                }
                if (ok1) {
                    __half2 ta = *reinterpret_cast<const __half2*>(tah + (size_t)s1 * 1024 + c);
                    __half2 tc = *reinterpret_cast<const __half2*>(tch + (size_t)o1 * 1024 + c);
                    float w0 = fmaxf(v10 + __low2float(ta) + __low2float(tc), 0.f);
                    float w1 = fmaxf(v11 + __high2float(ta) + __high2float(tc), 0.f);
                    *reinterpret_cast<__half2*>(Ch + (size_t)r1 * N + c) = __floats2half2_rn(w0, w1);
                }
            } else if (MODE == 8) {
                if (ok0) *reinterpret_cast<float2*>(Cf + (size_t)r0 * N + c) = make_float2(v00, v01);
                if (ok1) *reinterpret_cast<float2*>(Cf + (size_t)r1 * N + c) = make_float2(v10, v11);
            } else if (MODE == 9) {
                if (!part2) {
                    v00 = fmaxf(v00, 0.f); v01 = fmaxf(v01, 0.f);
                    v10 = fmaxf(v10, 0.f); v11 = fmaxf(v11, 0.f);
                    if (ok0) *reinterpret_cast<__half2*>(Ch + (size_t)r0 * N + c) = __floats2half2_rn(v00, v01);
                    if (ok1) *reinterpret_cast<__half2*>(Ch + (size_t)r1 * N + c) = __floats2half2_rn(v10, v11);
                } else {
                    if (ok0) {
                        float2 o = *reinterpret_cast<const float2*>(CfP + (size_t)r0 * N + c);
                        *reinterpret_cast<float2*>(CfP + (size_t)r0 * N + c) = make_float2(o.x + v00, o.y + v01);
                    }
                    if (ok1) {
                        float2 o = *reinterpret_cast<const float2*>(CfP + (size_t)r1 * N + c);
                        *reinterpret_cast<float2*>(CfP + (size_t)r1 * N + c) = make_float2(o.x + v10, o.y + v11);
                    }
                }
            } else { // MODE 2
                const int cl = c & 511;
                if (region == 1) {
                    if (ok0) *reinterpret_cast<float2*>(outp + (size_t)r0 * DIM + cl) = make_float2(v00, v01);
                    if (ok1) *reinterpret_cast<float2*>(outp + (size_t)r1 * DIM + cl) = make_float2(v10, v11);
                } else if (region == 0) {
                    if (ok0) red2(&pooled[(size_t)s0 * DIM + cl], v00, v01);
                    if (ok1) red2(&pooled[(size_t)s1 * DIM + cl], v10, v11);
                } else {
                    if (ok0) red2(&pooled[(size_t)o0 * DIM + cl], v00, v01);
                    if (ok1) red2(&pooled[(size_t)o1 * DIM + cl], v10, v11);
                }
            }
        }
    }
}

// ---------------- single merged prep kernel ----------------
constexpr size_t PP0 = 2560000;            // obj f4
constexpr size_t PP1 = PP0 + 12800000;     // pred f4
constexpr size_t PP2 = PP1 + 196608;       // W1 f4
constexpr size_t PP3 = PP2 + 196608;       // W2
constexpr size_t PP4 = PP3 + 65536;        // V1
constexpr size_t PP5 = PP4 + 65536;        // V2
constexpr size_t PP6 = PP5 + 65536;        // Po
constexpr size_t PP7 = PP6 + 65536;        // Pp
constexpr size_t PP8 = PP7 + 2560000;      // zero pooled (f4)
constexpr size_t PP9 = PP8 + 5000;         // zero counts (f4)
__global__ void prep_all_kernel(
    const float4* __restrict__ objv, const float4* __restrict__ predv,
    const float4* __restrict__ W1, const float4* __restrict__ W2,
    const float4* __restrict__ V1, const float4* __restrict__ V2,
    const float4* __restrict__ Po, const float4* __restrict__ Pp,
    uint2* __restrict__ objh, uint2* __restrict__ predh,
    uint2* __restrict__ w1h, uint2* __restrict__ w2h,
    uint2* __restrict__ v1h, uint2* __restrict__ v2h,
    uint2* __restrict__ poh, uint2* __restrict__ pph,
    float4* __restrict__ pooled, float4* __restrict__ counts)
{
    size_t i = (size_t)blockIdx.x * blockDim.x + threadIdx.x;
    if (i < PP0)      objh[i] = cvt4(objv[i]);
    else if (i < PP1) predh[i - PP0] = cvt4(predv[i - PP0]);
    else if (i < PP2) w1h[i - PP1] = cvt4(W1[i - PP1]);
    else if (i < PP3) w2h[i - PP2] = cvt4(W2[i - PP2]);
    else if (i < PP4) v1h[i - PP3] = cvt4(V1[i - PP3]);
    else if (i < PP5) v2h[i - PP4] = cvt4(V2[i - PP4]);
    else if (i < PP6) poh[i - PP5] = cvt4(Po[i - PP5]);
    else if (i < PP7) pph[i - PP6] = cvt4(Pp[i - PP6]);
    else if (i < PP8) pooled[i - PP7] = make_float4(0.f, 0.f, 0.f, 0.f);
    else if (i < PP9) counts[i - PP8] = make_float4(0.f, 0.f, 0.f, 0.f);
}

// count separate: counts must be fully zeroed first (no grid-wide ordering in-kernel)
__global__ void count_kernel(const int* __restrict__ edges, float* counts) {
    int i = blockIdx.x * blockDim.x + threadIdx.x;
    if (i < NTRI) {
        atomicAdd(&counts[edges[2 * i]], 1.f);
        atomicAdd(&counts[edges[2 * i + 1]], 1.f);
    }
}

__global__ void normalize_kernel(const float* __restrict__ pooled,
                                 const float* __restrict__ counts,
                                 __half* __restrict__ poolh) {
    int i = blockIdx.x * blockDim.x + threadIdx.x;
    if (i < NOBJ * DIM) {
        float c = counts[i >> 9];
        poolh[i] = __float2half_rn(pooled[i] * (1.f / fmaxf(c, 1.f)));
    }
}

// ---------------- launcher ----------------
extern "C" void kernel_launch(void* const* d_in, const int* in_sizes, int n_in,
                              void* d_out, int out_size)
{
    const float* objv    = (const float*)d_in[0];
    const float* predv   = (const float*)d_in[1];
    const int*   edges   = (const int*)  d_in[2];
    const float* W1      = (const float*)d_in[3];
    const float* b1      = (const float*)d_in[4];
    const float* W2      = (const float*)d_in[5];
    const float* b2      = (const float*)d_in[6];
    const float* V1      = (const float*)d_in[7];
    const float* c1      = (const float*)d_in[8];
    const float* V2      = (const float*)d_in[9];
    const float* c2      = (const float*)d_in[10];
    const float* P_obj   = (const float*)d_in[11];
    const float* pb_obj  = (const float*)d_in[12];
    const float* P_pred  = (const float*)d_in[13];
    const float* pb_pred = (const float*)d_in[14];

    __half *hh, *poolh, *gh, *objh, *predh, *tach, *w1h, *w2h, *v1h, *v2h, *poh, *pph;
    float *pooledp, *countsp;
    cudaGetSymbolAddress((void**)&hh,      g_hh);
    cudaGetSymbolAddress((void**)&pooledp, g_pooled);
    cudaGetSymbolAddress((void**)&poolh,   g_poolh);
    cudaGetSymbolAddress((void**)&gh,      g_gh);
    cudaGetSymbolAddress((void**)&countsp, g_counts);
    cudaGetSymbolAddress((void**)&objh,    g_objh);
    cudaGetSymbolAddress((void**)&predh,   g_predh);
    cudaGetSymbolAddress((void**)&tach,    g_tach);
    cudaGetSymbolAddress((void**)&w1h,     g_W1h);
    cudaGetSymbolAddress((void**)&w2h,     g_W2h);
    cudaGetSymbolAddress((void**)&v1h,     g_V1h);
    cudaGetSymbolAddress((void**)&v2h,     g_V2h);
    cudaGetSymbolAddress((void**)&poh,     g_Poh);
    cudaGetSymbolAddress((void**)&pph,     g_Pph);

    cudaFuncSetAttribute(gemm_h<2>, cudaFuncAttributeMaxDynamicSharedMemorySize, SMEM_BYTES);
    cudaFuncSetAttribute(gemm_h<4>, cudaFuncAttributeMaxDynamicSharedMemorySize, SMEM_BYTES);
    cudaFuncSetAttribute(gemm_h<6>, cudaFuncAttributeMaxDynamicSharedMemorySize, SMEM_BYTES);
    cudaFuncSetAttribute(gemm_h<8>, cudaFuncAttributeMaxDynamicSharedMemorySize, SMEM_BYTES);
    cudaFuncSetAttribute(gemm_h<9>, cudaFuncAttributeMaxDynamicSharedMemorySize, SMEM_BYTES);

    float* out_obj = (float*)d_out;
    float* out_p   = (float*)d_out + (size_t)NOBJ * DIM;

    const int gMtri = (NTRI + BM - 1) / BM;   // 782
    const int gMobj = (NOBJ + BM - 1) / BM;   // 157

    // 0: all conversions + zero fills in one kernel
    prep_all_kernel<<<(unsigned)((PP9 + 255) / 256), 256>>>(
        (const float4*)objv, (const float4*)predv,
        (const float4*)W1, (const float4*)W2, (const float4*)V1, (const float4*)V2,
        (const float4*)P_obj, (const float4*)P_pred,
        (uint2*)objh, (uint2*)predh,
        (uint2*)w1h, (uint2*)w2h, (uint2*)v1h, (uint2*)v2h, (uint2*)poh, (uint2*)pph,
        (float4*)pooledp, (float4*)countsp);

    // 1: counts (after counts zeroed)
    count_kernel<<<(NTRI + 255) / 256, 256>>>(edges, countsp);

    // 2: [T_a | T_c] = obj @ [W1a | W1c]^T  (merged, N=1024, split-B addressing)
    gemm_h<6><<<dim3(8, gMobj), NTHR, SMEM_BYTES>>>(
        objh, w1h, 1536, nullptr, tach, nullptr, NOBJ, 1024, 512,
        nullptr, nullptr, nullptr, nullptr, nullptr, nullptr, nullptr, 0);

    // 3: h = relu(pred @ W1b^T + T_a[s] + T_c[o] + b1)
    gemm_h<4><<<dim3(4, gMtri), NTHR, SMEM_BYTES>>>(
        predh, w1h + 512, 1536, b1, hh, nullptr, NTRI, 512, 512,
        edges, tach, tach + 512, nullptr, nullptr, nullptr, nullptr, 0);

    // 4: G2: new_t = relu(h @ W2^T + b2); split -> pooled reds + out_p
    gemm_h<2><<<dim3(12, gMtri), NTHR, SMEM_BYTES>>>(
        hh, w2h, 512, b2, nullptr, nullptr, NTRI, 1536, 512,
        edges, nullptr, nullptr, pooledp, out_p, nullptr, nullptr, 0);

    // 5: pooled /= max(counts,1) -> half
    normalize_kernel<<<(NOBJ * DIM + 255) / 256, 256>>>(pooledp, countsp, poolh);

    // 6: G3 || G6 packed (MODE 9):
    //    rows [0,157):  gh = relu(pooled @ V1^T + c1)            (half)
    //    rows [157,..): out_p += pred @ P_pred^T + pb_pred       (float +=)
    gemm_h<9><<<dim3(4, gMobj + gMtri), NTHR, SMEM_BYTES>>>(
        poolh, v1h, 512, c1, gh, nullptr, NOBJ, 512, 512,
        nullptr, predh, pph, nullptr, nullptr, pb_pred, out_p, NTRI);

    // 7: G4+G5 fused (MODE 8):
    //    out_obj = relu(g @ V2^T + c2) + obj @ P_obj^T + pb_obj  (single pass, 1 store)
    gemm_h<8><<<dim3(4, gMobj), NTHR, SMEM_BYTES>>>(
        gh, v2h, 512, c2, nullptr, out_obj, NOBJ, 512, 512,
        nullptr, objh, poh, nullptr, nullptr, pb_obj, nullptr, 0);
}